// round 8
// baseline (speedup 1.0000x reference)
#include <cuda_runtime.h>
#include <cuda_fp16.h>
#include <cuda_bf16.h>
#include <cstdint>
#include <math.h>

// Problem constants
#define GM 8192      // B*S
#define GN 1024      // D_MODEL
#define GK 1024      // D_MODEL
#define SQ 2048      // S
#define NB 4         // B
#define NH 16        // heads
#define DKH 64       // d_k per head

// Scratch (allocation-free rule: __device__ globals)
__device__ float  g_ctx[(size_t)GM * GN];
__device__ __half g_hQ[(size_t)GM * GN];
__device__ __half g_hK[(size_t)GM * GN];
__device__ __half g_hV[(size_t)GM * GN];
// fp16 inputs for single-pass Q/K/V projections
__device__ __half g_a16[3][(size_t)GM * GK];
__device__ __half g_w16[3][(size_t)GN * GK];
// bf16 hi/lo split buffers (O projection, 3-pass)
__device__ __nv_bfloat16 g_act_hi[(size_t)GM * GK];
__device__ __nv_bfloat16 g_act_lo[(size_t)GM * GK];
__device__ __nv_bfloat16 g_w_hi[(size_t)GN * GK];
__device__ __nv_bfloat16 g_w_lo[(size_t)GN * GK];

__device__ __forceinline__ uint32_t smem_u32(const void* p) {
    uint32_t a;
    asm("{ .reg .u64 t; cvta.to.shared.u64 t, %1; cvt.u32.u64 %0, t; }"
        : "=r"(a) : "l"(p));
    return a;
}

__device__ __forceinline__ void cp_async16(uint32_t sm, const void* g) {
    asm volatile("cp.async.cg.shared.global [%0], [%1], 16;\n"
                 :: "r"(sm), "l"(g));
}
#define CP_COMMIT() asm volatile("cp.async.commit_group;\n" ::: "memory")
#define CP_WAIT(N)  asm volatile("cp.async.wait_group %0;\n" :: "n"(N) : "memory")

__device__ __forceinline__ void ldmx4(uint32_t* r, uint32_t addr) {
    asm volatile("ldmatrix.sync.aligned.m8n8.x4.shared.b16 {%0,%1,%2,%3}, [%4];"
                 : "=r"(r[0]), "=r"(r[1]), "=r"(r[2]), "=r"(r[3]) : "r"(addr));
}
__device__ __forceinline__ void ldmx4t(uint32_t* r, uint32_t addr) {
    asm volatile("ldmatrix.sync.aligned.m8n8.x4.trans.shared.b16 {%0,%1,%2,%3}, [%4];"
                 : "=r"(r[0]), "=r"(r[1]), "=r"(r[2]), "=r"(r[3]) : "r"(addr));
}

__device__ __forceinline__ void mma_bf(float* c, const uint32_t* a,
                                       uint32_t b0, uint32_t b1) {
    asm volatile(
        "mma.sync.aligned.m16n8k16.row.col.f32.bf16.bf16.f32 "
        "{%0,%1,%2,%3}, {%4,%5,%6,%7}, {%8,%9}, {%0,%1,%2,%3};"
        : "+f"(c[0]), "+f"(c[1]), "+f"(c[2]), "+f"(c[3])
        : "r"(a[0]), "r"(a[1]), "r"(a[2]), "r"(a[3]), "r"(b0), "r"(b1));
}
__device__ __forceinline__ void mma_fp(float* c, const uint32_t* a,
                                       uint32_t b0, uint32_t b1) {
    asm volatile(
        "mma.sync.aligned.m16n8k16.row.col.f32.f16.f16.f32 "
        "{%0,%1,%2,%3}, {%4,%5,%6,%7}, {%8,%9}, {%0,%1,%2,%3};"
        : "+f"(c[0]), "+f"(c[1]), "+f"(c[2]), "+f"(c[3])
        : "r"(a[0]), "r"(a[1]), "r"(a[2]), "r"(a[3]), "r"(b0), "r"(b1));
}

__device__ __forceinline__ uint32_t pack_h2(float x, float y) {
    const half2 h = __floats2half2_rn(x, y);
    return *reinterpret_cast<const uint32_t*>(&h);
}

// ============================================================================
// fp32 -> fp16 convert, 3 tensors per launch (z selects)
// ============================================================================
__global__ __launch_bounds__(256) void conv_fp16_x3(
    const float4* __restrict__ s0, const float4* __restrict__ s1,
    const float4* __restrict__ s2, half2* __restrict__ d0,
    half2* __restrict__ d1, half2* __restrict__ d2, int n4)
{
    const int z = blockIdx.y;
    const float4* src = (z == 0) ? s0 : (z == 1) ? s1 : s2;
    half2* dst = (z == 0) ? d0 : (z == 1) ? d1 : d2;
    const int i = blockIdx.x * 256 + threadIdx.x;
    if (i >= n4) return;
    const float4 v = src[i];
    dst[2 * i]     = __floats2half2_rn(v.x, v.y);
    dst[2 * i + 1] = __floats2half2_rn(v.z, v.w);
}

// ============================================================================
// fp32 -> (bf16 hi, bf16 lo) split (O projection path)
// ============================================================================
__global__ __launch_bounds__(256) void split_bf16(
    const float4* __restrict__ src, __nv_bfloat162* __restrict__ hi,
    __nv_bfloat162* __restrict__ lo, int n4)
{
    const int i = blockIdx.x * 256 + threadIdx.x;
    if (i >= n4) return;
    const float4 v = src[i];
    const __nv_bfloat16 h0 = __float2bfloat16_rn(v.x);
    const __nv_bfloat16 h1 = __float2bfloat16_rn(v.y);
    const __nv_bfloat16 h2 = __float2bfloat16_rn(v.z);
    const __nv_bfloat16 h3 = __float2bfloat16_rn(v.w);
    const __nv_bfloat16 l0 = __float2bfloat16_rn(v.x - __bfloat162float(h0));
    const __nv_bfloat16 l1 = __float2bfloat16_rn(v.y - __bfloat162float(h1));
    const __nv_bfloat16 l2 = __float2bfloat16_rn(v.z - __bfloat162float(h2));
    const __nv_bfloat16 l3 = __float2bfloat16_rn(v.w - __bfloat162float(h3));
    hi[2 * i]     = __halves2bfloat162(h0, h1);
    hi[2 * i + 1] = __halves2bfloat162(h2, h3);
    lo[2 * i]     = __halves2bfloat162(l0, l1);
    lo[2 * i + 1] = __halves2bfloat162(l2, l3);
}

#define BM 128
#define BN 128
#define BKC 32
#define PADK 40

// ============================================================================
// Single-pass fp16 GEMM for Q/K/V projections, fused via blockIdx.z.
// ============================================================================
__global__ __launch_bounds__(256, 2) void gemm_qkv_fp16(
    const __half* __restrict__ A0, const __half* __restrict__ A1,
    const __half* __restrict__ A2, const __half* __restrict__ W0,
    const __half* __restrict__ W1, const __half* __restrict__ W2,
    const float* __restrict__ b0p, const float* __restrict__ b1p,
    const float* __restrict__ b2p, __half* __restrict__ C0,
    __half* __restrict__ C1, __half* __restrict__ C2)
{
    __shared__ __align__(16) __half smA[2][BM * PADK];
    __shared__ __align__(16) __half smB[2][BN * PADK];

    const int z = blockIdx.z;
    const __half* A = (z == 0) ? A0 : (z == 1) ? A1 : A2;
    const __half* W = (z == 0) ? W0 : (z == 1) ? W1 : W2;
    const float* bias = (z == 0) ? b0p : (z == 1) ? b1p : b2p;
    __half* C = (z == 0) ? C0 : (z == 1) ? C1 : C2;

    const int tid  = threadIdx.x;
    const int wid  = tid >> 5;
    const int lane = tid & 31;
    const int wm   = wid & 3;
    const int wn   = wid >> 2;
    const int m0   = blockIdx.y * BM;
    const int n0   = blockIdx.x * BN;

    const int crow = tid >> 1;
    const int cs0  = (tid & 1) * 2;

    float acc[2][8][4];
#pragma unroll
    for (int i = 0; i < 2; i++)
#pragma unroll
        for (int j = 0; j < 8; j++)
#pragma unroll
            for (int k = 0; k < 4; k++) acc[i][j][k] = 0.0f;

    const uint32_t smA0 = smem_u32(&smA[0][0]);
    const uint32_t smB0 = smem_u32(&smB[0][0]);

    auto issue_copy = [&](int it, int st) {
        const int kb = it * BKC;
        const __half* Ab = A + (size_t)(m0 + crow) * GK + kb;
        const __half* Bb = W + (size_t)(n0 + crow) * GK + kb;
        const uint32_t sa = smA0 + (st * BM * PADK + crow * PADK) * 2;
        const uint32_t sb = smB0 + (st * BN * PADK + crow * PADK) * 2;
#pragma unroll
        for (int s = 0; s < 2; s++) {
            cp_async16(sa + (cs0 + s) * 16, Ab + (cs0 + s) * 8);
            cp_async16(sb + (cs0 + s) * 16, Bb + (cs0 + s) * 8);
        }
        CP_COMMIT();
    };

    issue_copy(0, 0);

    const int NIT1 = GK / BKC;
    for (int it = 0; it < NIT1; it++) {
        const int st = it & 1;
        if (it + 1 < NIT1) {
            issue_copy(it + 1, st ^ 1);
            CP_WAIT(1);
        } else {
            CP_WAIT(0);
        }
        __syncthreads();

        const uint32_t baseA = smA0 + st * BM * PADK * 2;
        const uint32_t baseB = smB0 + st * BN * PADK * 2;
        const int lr = lane & 15;
        const int lc = (lane >> 4) * 8;
#pragma unroll
        for (int ks = 0; ks < 2; ks++) {
            uint32_t a[2][4], b[4][4];
#pragma unroll
            for (int am = 0; am < 2; am++) {
                const int row = wm * 32 + am * 16 + lr;
                ldmx4(a[am], baseA + (row * PADK + ks * 16 + lc) * 2);
            }
#pragma unroll
            for (int bn = 0; bn < 4; bn++) {
                const int row = wn * 64 + bn * 16 + lr;
                ldmx4(b[bn], baseB + (row * PADK + ks * 16 + lc) * 2);
            }
#pragma unroll
            for (int am = 0; am < 2; am++)
#pragma unroll
                for (int bn = 0; bn < 4; bn++) {
                    mma_fp(acc[am][2 * bn + 0], a[am], b[bn][0], b[bn][2]);
                    mma_fp(acc[am][2 * bn + 1], a[am], b[bn][1], b[bn][3]);
                }
        }
        __syncthreads();
    }

    const int er = lane >> 2;
    const int ec = (lane & 3) * 2;
#pragma unroll
    for (int am = 0; am < 2; am++) {
        const int row = m0 + wm * 32 + am * 16 + er;
#pragma unroll
        for (int bn = 0; bn < 8; bn++) {
            const int col = n0 + wn * 64 + bn * 8 + ec;
            const float bx = bias[col], by = bias[col + 1];
            *(half2*)(C + (size_t)row * GN + col) =
                __floats2half2_rn(acc[am][bn][0] + bx, acc[am][bn][1] + by);
            *(half2*)(C + (size_t)(row + 8) * GN + col) =
                __floats2half2_rn(acc[am][bn][2] + bx, acc[am][bn][3] + by);
        }
    }
}

// ============================================================================
// 3-pass bf16 hi/lo GEMM (O projection): C = A @ W^T + bias, fp32 out.
// ============================================================================
#define NIT  (3 * (GK / BKC))    // 96

__global__ __launch_bounds__(256, 2) void gemm_mma_f32(
    const __nv_bfloat16* __restrict__ Ah, const __nv_bfloat16* __restrict__ Al,
    const __nv_bfloat16* __restrict__ Wh, const __nv_bfloat16* __restrict__ Wl,
    const float* __restrict__ bias, float* __restrict__ C)
{
    __shared__ __align__(16) __nv_bfloat16 smA[2][BM * PADK];
    __shared__ __align__(16) __nv_bfloat16 smB[2][BN * PADK];

    const int tid  = threadIdx.x;
    const int wid  = tid >> 5;
    const int lane = tid & 31;
    const int wm   = wid & 3;
    const int wn   = wid >> 2;
    const int m0   = blockIdx.y * BM;
    const int n0   = blockIdx.x * BN;

    const __nv_bfloat16* Aptr[3] = {Ah, Ah, Al};
    const __nv_bfloat16* Bptr[3] = {Wh, Wl, Wh};

    const int crow = tid >> 1;
    const int cs0  = (tid & 1) * 2;

    float acc[2][8][4];
#pragma unroll
    for (int i = 0; i < 2; i++)
#pragma unroll
        for (int j = 0; j < 8; j++)
#pragma unroll
            for (int k = 0; k < 4; k++) acc[i][j][k] = 0.0f;

    const uint32_t smA0 = smem_u32(&smA[0][0]);
    const uint32_t smB0 = smem_u32(&smB[0][0]);

    auto issue_copy = [&](int it, int st) {
        const int p  = it >> 5;
        const int kb = (it & 31) * BKC;
        const __nv_bfloat16* Ab = Aptr[p] + (size_t)(m0 + crow) * GK + kb;
        const __nv_bfloat16* Bb = Bptr[p] + (size_t)(n0 + crow) * GK + kb;
        const uint32_t sa = smA0 + (st * BM * PADK + crow * PADK) * 2;
        const uint32_t sb = smB0 + (st * BN * PADK + crow * PADK) * 2;
#pragma unroll
        for (int s = 0; s < 2; s++) {
            cp_async16(sa + (cs0 + s) * 16, Ab + (cs0 + s) * 8);
            cp_async16(sb + (cs0 + s) * 16, Bb + (cs0 + s) * 8);
        }
        CP_COMMIT();
    };

    issue_copy(0, 0);

    for (int it = 0; it < NIT; it++) {
        const int st = it & 1;
        if (it + 1 < NIT) {
            issue_copy(it + 1, st ^ 1);
            CP_WAIT(1);
        } else {
            CP_WAIT(0);
        }
        __syncthreads();

        const uint32_t baseA = smA0 + st * BM * PADK * 2;
        const uint32_t baseB = smB0 + st * BN * PADK * 2;
        const int lr = lane & 15;
        const int lc = (lane >> 4) * 8;
#pragma unroll
        for (int ks = 0; ks < 2; ks++) {
            uint32_t a[2][4], b[4][4];
#pragma unroll
            for (int am = 0; am < 2; am++) {
                const int row = wm * 32 + am * 16 + lr;
                ldmx4(a[am], baseA + (row * PADK + ks * 16 + lc) * 2);
            }
#pragma unroll
            for (int bn = 0; bn < 4; bn++) {
                const int row = wn * 64 + bn * 16 + lr;
                ldmx4(b[bn], baseB + (row * PADK + ks * 16 + lc) * 2);
            }
#pragma unroll
            for (int am = 0; am < 2; am++)
#pragma unroll
                for (int bn = 0; bn < 4; bn++) {
                    mma_bf(acc[am][2 * bn + 0], a[am], b[bn][0], b[bn][2]);
                    mma_bf(acc[am][2 * bn + 1], a[am], b[bn][1], b[bn][3]);
                }
        }
        __syncthreads();
    }

    const int er = lane >> 2;
    const int ec = (lane & 3) * 2;
#pragma unroll
    for (int am = 0; am < 2; am++) {
        const int row = m0 + wm * 32 + am * 16 + er;
#pragma unroll
        for (int bn = 0; bn < 8; bn++) {
            const int col = n0 + wn * 64 + bn * 8 + ec;
            const float bx = bias[col], by = bias[col + 1];
            *(float2*)(C + (size_t)row * GN + col) =
                make_float2(acc[am][bn][0] + bx, acc[am][bn][1] + by);
            *(float2*)(C + (size_t)(row + 8) * GN + col) =
                make_float2(acc[am][bn][2] + bx, acc[am][bn][3] + by);
        }
    }
}

// ============================================================================
// Fused flash attention, fp16 mma.sync, register-resident P (flash-v2 style).
//   BQ=128 (8 warps x 16 rows), BKV=64, K/V double-buffered cp.async.
//   P: QK C-fragments converted in-register to PV A-fragments (no smem trip).
//   smem 54KB -> 2 CTAs/SM.
// ============================================================================
#define BQ 128
#define BKV 64
#define QS 72
#define NTKV (SQ / BKV)   // 32
#define ATTN_SMEM ((BQ * QS + 4 * BKV * QS) * 2)   // 55296 B

__global__ __launch_bounds__(256, 2) void attn_mma(
    const __half* __restrict__ Qh, const __half* __restrict__ Kh,
    const __half* __restrict__ Vh, float* __restrict__ Ctx)
{
    extern __shared__ __half sm[];
    __half* sQ = sm;                   // [128][QS]
    __half* sK = sQ + BQ * QS;         // [2][64][QS]
    __half* sV = sK + 2 * BKV * QS;    // [2][64][QS]

    const int tid  = threadIdx.x;
    const int wid  = tid >> 5;
    const int lane = tid & 31;
    const int lr   = lane & 15;
    const int lc   = (lane >> 4) * 8;
    const int er   = lane >> 2;
    const int ec   = (lane & 3) * 2;
    const int wrow = wid * 16;

    const int q0 = blockIdx.x * BQ;
    const size_t hb = ((size_t)blockIdx.z * SQ) * (size_t)GN + (size_t)blockIdx.y * DKH;

    const uint32_t sQb = smem_u32(sQ);
    const uint32_t sKb = smem_u32(sK);
    const uint32_t sVb = smem_u32(sV);

    // K/V copy mapping: 64 rows, 4 threads/row, 2x16B segments each
    const int crow = tid >> 2;
    const int cs0  = (tid & 3) * 2;

    auto loadKV = [&](int kt, int st) {
        const __half* kp = Kh + hb + (size_t)(kt * BKV + crow) * GN;
        const __half* vp = Vh + hb + (size_t)(kt * BKV + crow) * GN;
        const uint32_t dk = sKb + (st * BKV * QS + crow * QS) * 2;
        const uint32_t dv = sVb + (st * BKV * QS + crow * QS) * 2;
#pragma unroll
        for (int s = 0; s < 2; s++) {
            cp_async16(dk + (cs0 + s) * 16, kp + (cs0 + s) * 8);
            cp_async16(dv + (cs0 + s) * 16, vp + (cs0 + s) * 8);
        }
    };

    // prologue: Q (128 rows, 2 threads/row, 4 segs) + KV tile 0, then KV tile 1
    {
        const int qrow = tid >> 1;
        const int qs0  = (tid & 1) * 4;
        const __half* qp = Qh + hb + (size_t)(q0 + qrow) * GN;
        const uint32_t dq = sQb + (qrow * QS) * 2;
#pragma unroll
        for (int s = 0; s < 4; s++)
            cp_async16(dq + (qs0 + s) * 16, qp + (qs0 + s) * 8);
    }
    loadKV(0, 0);
    CP_COMMIT();
    loadKV(1, 1);
    CP_COMMIT();

    float m0r = -1.0e30f, m1r = -1.0e30f, l0 = 0.0f, l1 = 0.0f;
    float o[8][4];
#pragma unroll
    for (int j = 0; j < 8; j++)
#pragma unroll
        for (int k = 0; k < 4; k++) o[j][k] = 0.0f;

    uint32_t aq[4][4];   // Q fragments, loaded once

    for (int kt = 0; kt < NTKV; kt++) {
        if (kt < NTKV - 1) { CP_WAIT(1); } else { CP_WAIT(0); }
        __syncthreads();
        if (kt == 0) {
#pragma unroll
            for (int ks = 0; ks < 4; ks++)
                ldmx4(aq[ks], sQb + ((wrow + lr) * QS + ks * 16 + lc) * 2);
        }
        const int st = kt & 1;
        const uint32_t kbase = sKb + st * BKV * QS * 2;
        const uint32_t vbase = sVb + st * BKV * QS * 2;

        // ---- S = Q K^T (16 x 64 per warp) ----
        float s[8][4];
#pragma unroll
        for (int t = 0; t < 8; t++)
#pragma unroll
            for (int k = 0; k < 4; k++) s[t][k] = 0.0f;

#pragma unroll
        for (int ks = 0; ks < 4; ks++) {
#pragma unroll
            for (int nt = 0; nt < 4; nt++) {
                uint32_t b[4];
                ldmx4(b, kbase + ((nt * 16 + lr) * QS + ks * 16 + lc) * 2);
                mma_fp(s[2 * nt + 0], aq[ks], b[0], b[2]);
                mma_fp(s[2 * nt + 1], aq[ks], b[1], b[3]);
            }
        }

        // ---- online softmax; P packed into A-frag registers ----
        float mx0 = -1.0e30f, mx1 = -1.0e30f;
#pragma unroll
        for (int t = 0; t < 8; t++) {
            mx0 = fmaxf(mx0, fmaxf(s[t][0], s[t][1]));
            mx1 = fmaxf(mx1, fmaxf(s[t][2], s[t][3]));
        }
        mx0 = fmaxf(mx0, __shfl_xor_sync(0xffffffffu, mx0, 1));
        mx0 = fmaxf(mx0, __shfl_xor_sync(0xffffffffu, mx0, 2));
        mx1 = fmaxf(mx1, __shfl_xor_sync(0xffffffffu, mx1, 1));
        mx1 = fmaxf(mx1, __shfl_xor_sync(0xffffffffu, mx1, 2));
        mx0 *= 0.125f;
        mx1 *= 0.125f;
        const float mn0 = fmaxf(m0r, mx0);
        const float mn1 = fmaxf(m1r, mx1);
        const float c0 = __expf(m0r - mn0);
        const float c1 = __expf(m1r - mn1);

        float rs0 = 0.0f, rs1 = 0.0f;
        uint32_t pw[8][2];
#pragma unroll
        for (int t = 0; t < 8; t++) {
            const float p00 = __expf(fmaf(s[t][0], 0.125f, -mn0));
            const float p01 = __expf(fmaf(s[t][1], 0.125f, -mn0));
            const float p10 = __expf(fmaf(s[t][2], 0.125f, -mn1));
            const float p11 = __expf(fmaf(s[t][3], 0.125f, -mn1));
            rs0 += p00 + p01;
            rs1 += p10 + p11;
            pw[t][0] = pack_h2(p00, p01);
            pw[t][1] = pack_h2(p10, p11);
        }
        rs0 += __shfl_xor_sync(0xffffffffu, rs0, 1);
        rs0 += __shfl_xor_sync(0xffffffffu, rs0, 2);
        rs1 += __shfl_xor_sync(0xffffffffu, rs1, 1);
        rs1 += __shfl_xor_sync(0xffffffffu, rs1, 2);
        l0 = l0 * c0 + rs0;
        l1 = l1 * c1 + rs1;
        m0r = mn0;
        m1r = mn1;
#pragma unroll
        for (int j = 0; j < 8; j++) {
            o[j][0] *= c0; o[j][1] *= c0;
            o[j][2] *= c1; o[j][3] *= c1;
        }

        // ---- O += P V (P from registers, V via ldmatrix.trans) ----
#pragma unroll
        for (int j = 0; j < 4; j++) {      // 16-key chunks
            const uint32_t pa[4] = {pw[2 * j][0], pw[2 * j][1],
                                    pw[2 * j + 1][0], pw[2 * j + 1][1]};
#pragma unroll
            for (int dt = 0; dt < 4; dt++) {
                uint32_t vb[4];
                ldmx4t(vb, vbase + ((j * 16 + lr) * QS + dt * 16 + lc) * 2);
                mma_fp(o[2 * dt + 0], pa, vb[0], vb[1]);
                mma_fp(o[2 * dt + 1], pa, vb[2], vb[3]);
            }
        }
        __syncthreads();   // all warps done with stage st before refill
        if (kt + 2 < NTKV) {
            loadKV(kt + 2, st);
            CP_COMMIT();
        }
    }

    const float inv0 = 1.0f / l0;
    const float inv1 = 1.0f / l1;
    const int row0 = q0 + wrow + er;
#pragma unroll
    for (int j = 0; j < 8; j++) {
        const int col = j * 8 + ec;
        float* p0 = Ctx + hb + (size_t)row0 * GN + col;
        float* p1 = Ctx + hb + (size_t)(row0 + 8) * GN + col;
        *(float2*)p0 = make_float2(o[j][0] * inv0, o[j][1] * inv0);
        *(float2*)p1 = make_float2(o[j][2] * inv1, o[j][3] * inv1);
    }
}

// ============================================================================
// Launch
// ============================================================================
extern "C" void kernel_launch(void* const* d_in, const int* in_sizes, int n_in,
                              void* d_out, int out_size)
{
    const float* q  = (const float*)d_in[0];
    const float* k  = (const float*)d_in[1];
    const float* v  = (const float*)d_in[2];
    const float* Wq = (const float*)d_in[3];
    const float* bq = (const float*)d_in[4];
    const float* Wk = (const float*)d_in[5];
    const float* bk = (const float*)d_in[6];
    const float* Wv = (const float*)d_in[7];
    const float* bv = (const float*)d_in[8];
    const float* Wo = (const float*)d_in[9];
    const float* bo = (const float*)d_in[10];
    float* out = (float*)d_out;

    float* dC;
    __half *hQ, *hK, *hV, *a16, *w16;
    __nv_bfloat16 *ah, *al, *wh, *wl;
    cudaGetSymbolAddress((void**)&dC, g_ctx);
    cudaGetSymbolAddress((void**)&hQ, g_hQ);
    cudaGetSymbolAddress((void**)&hK, g_hK);
    cudaGetSymbolAddress((void**)&hV, g_hV);
    cudaGetSymbolAddress((void**)&a16, g_a16);
    cudaGetSymbolAddress((void**)&w16, g_w16);
    cudaGetSymbolAddress((void**)&ah, g_act_hi);
    cudaGetSymbolAddress((void**)&al, g_act_lo);
    cudaGetSymbolAddress((void**)&wh, g_w_hi);
    cudaGetSymbolAddress((void**)&wl, g_w_lo);

    __half* a0 = a16;
    __half* a1 = a16 + (size_t)GM * GK;
    __half* a2 = a16 + 2 * (size_t)GM * GK;
    __half* w0 = w16;
    __half* w1 = w16 + (size_t)GN * GK;
    __half* w2 = w16 + 2 * (size_t)GN * GK;

    const int n4_act = GM * GK / 4;
    const int n4_w   = GN * GK / 4;

    conv_fp16_x3<<<dim3(n4_act / 256, 3), 256>>>(
        (const float4*)q, (const float4*)k, (const float4*)v,
        (half2*)a0, (half2*)a1, (half2*)a2, n4_act);
    conv_fp16_x3<<<dim3(n4_w / 256, 3), 256>>>(
        (const float4*)Wq, (const float4*)Wk, (const float4*)Wv,
        (half2*)w0, (half2*)w1, (half2*)w2, n4_w);

    gemm_qkv_fp16<<<dim3(GN / BN, GM / BM, 3), 256>>>(
        a0, a1, a2, w0, w1, w2, bq, bk, bv, hQ, hK, hV);

    cudaFuncSetAttribute(attn_mma, cudaFuncAttributeMaxDynamicSharedMemorySize, ATTN_SMEM);
    attn_mma<<<dim3(SQ / BQ, NH, NB), 256, ATTN_SMEM>>>(hQ, hK, hV, dC);

    split_bf16<<<(n4_act + 255) / 256, 256>>>((const float4*)dC,
        (__nv_bfloat162*)ah, (__nv_bfloat162*)al, n4_act);
    split_bf16<<<(n4_w + 255) / 256, 256>>>((const float4*)Wo,
        (__nv_bfloat162*)wh, (__nv_bfloat162*)wl, n4_w);
    gemm_mma_f32<<<dim3(GN / BN, GM / BM), 256>>>(ah, al, wh, wl, bo, out);
}

// round 9
// speedup vs baseline: 1.6416x; 1.6416x over previous
#include <cuda_runtime.h>
#include <cuda_fp16.h>
#include <cuda_bf16.h>
#include <cstdint>
#include <math.h>

// Problem constants
#define GM 8192      // B*S
#define GN 1024      // D_MODEL
#define GK 1024      // D_MODEL
#define SQ 2048      // S
#define NB 4         // B
#define NH 16        // heads
#define DKH 64       // d_k per head

// Scratch (allocation-free rule: __device__ globals)
__device__ __half g_hQ[(size_t)GM * GN];
__device__ __half g_hK[(size_t)GM * GN];
__device__ __half g_hV[(size_t)GM * GN];
__device__ __half g_hC[(size_t)GM * GN];      // fp16 ctx
// fp16 inputs for single-pass Q/K/V projections
__device__ __half g_a16[3][(size_t)GM * GK];
__device__ __half g_w16[3][(size_t)GN * GK];
// fp16 hi/lo split of Wo (lo pre-scaled by 2^10)
__device__ __half g_woh[(size_t)GN * GK];
__device__ __half g_wol[(size_t)GN * GK];

__device__ __forceinline__ uint32_t smem_u32(const void* p) {
    uint32_t a;
    asm("{ .reg .u64 t; cvta.to.shared.u64 t, %1; cvt.u32.u64 %0, t; }"
        : "=r"(a) : "l"(p));
    return a;
}

__device__ __forceinline__ void cp_async16(uint32_t sm, const void* g) {
    asm volatile("cp.async.cg.shared.global [%0], [%1], 16;\n"
                 :: "r"(sm), "l"(g));
}
#define CP_COMMIT() asm volatile("cp.async.commit_group;\n" ::: "memory")
#define CP_WAIT(N)  asm volatile("cp.async.wait_group %0;\n" :: "n"(N) : "memory")

__device__ __forceinline__ void ldmx4(uint32_t* r, uint32_t addr) {
    asm volatile("ldmatrix.sync.aligned.m8n8.x4.shared.b16 {%0,%1,%2,%3}, [%4];"
                 : "=r"(r[0]), "=r"(r[1]), "=r"(r[2]), "=r"(r[3]) : "r"(addr));
}
__device__ __forceinline__ void ldmx4t(uint32_t* r, uint32_t addr) {
    asm volatile("ldmatrix.sync.aligned.m8n8.x4.trans.shared.b16 {%0,%1,%2,%3}, [%4];"
                 : "=r"(r[0]), "=r"(r[1]), "=r"(r[2]), "=r"(r[3]) : "r"(addr));
}

__device__ __forceinline__ void mma_fp(float* c, const uint32_t* a,
                                       uint32_t b0, uint32_t b1) {
    asm volatile(
        "mma.sync.aligned.m16n8k16.row.col.f32.f16.f16.f32 "
        "{%0,%1,%2,%3}, {%4,%5,%6,%7}, {%8,%9}, {%0,%1,%2,%3};"
        : "+f"(c[0]), "+f"(c[1]), "+f"(c[2]), "+f"(c[3])
        : "r"(a[0]), "r"(a[1]), "r"(a[2]), "r"(a[3]), "r"(b0), "r"(b1));
}

__device__ __forceinline__ uint32_t pack_h2(float x, float y) {
    const half2 h = __floats2half2_rn(x, y);
    return *reinterpret_cast<const uint32_t*>(&h);
}

// ============================================================================
// fp32 -> fp16 convert, 3 tensors per launch (z selects)
// ============================================================================
__global__ __launch_bounds__(256) void conv_fp16_x3(
    const float4* __restrict__ s0, const float4* __restrict__ s1,
    const float4* __restrict__ s2, half2* __restrict__ d0,
    half2* __restrict__ d1, half2* __restrict__ d2, int n4)
{
    const int z = blockIdx.y;
    const float4* src = (z == 0) ? s0 : (z == 1) ? s1 : s2;
    half2* dst = (z == 0) ? d0 : (z == 1) ? d1 : d2;
    const int i = blockIdx.x * 256 + threadIdx.x;
    if (i >= n4) return;
    const float4 v = src[i];
    dst[2 * i]     = __floats2half2_rn(v.x, v.y);
    dst[2 * i + 1] = __floats2half2_rn(v.z, v.w);
}

// ============================================================================
// fp32 -> fp16 (hi, lo*2^10) split, for Wo
// ============================================================================
__global__ __launch_bounds__(256) void split_fp16w(
    const float4* __restrict__ src, half2* __restrict__ hi,
    half2* __restrict__ lo, int n4)
{
    const int i = blockIdx.x * 256 + threadIdx.x;
    if (i >= n4) return;
    const float4 v = src[i];
    const __half h0 = __float2half_rn(v.x);
    const __half h1 = __float2half_rn(v.y);
    const __half h2 = __float2half_rn(v.z);
    const __half h3 = __float2half_rn(v.w);
    hi[2 * i]     = __halves2half2(h0, h1);
    hi[2 * i + 1] = __halves2half2(h2, h3);
    lo[2 * i]     = __floats2half2_rn((v.x - __half2float(h0)) * 1024.0f,
                                      (v.y - __half2float(h1)) * 1024.0f);
    lo[2 * i + 1] = __floats2half2_rn((v.z - __half2float(h2)) * 1024.0f,
                                      (v.w - __half2float(h3)) * 1024.0f);
}

#define BM 128
#define BN 128
#define BKC 32
#define PADK 40

// ============================================================================
// Single-pass fp16 GEMM for Q/K/V projections, fused via blockIdx.z.
// ============================================================================
__global__ __launch_bounds__(256, 2) void gemm_qkv_fp16(
    const __half* __restrict__ A0, const __half* __restrict__ A1,
    const __half* __restrict__ A2, const __half* __restrict__ W0,
    const __half* __restrict__ W1, const __half* __restrict__ W2,
    const float* __restrict__ b0p, const float* __restrict__ b1p,
    const float* __restrict__ b2p, __half* __restrict__ C0,
    __half* __restrict__ C1, __half* __restrict__ C2)
{
    __shared__ __align__(16) __half smA[2][BM * PADK];
    __shared__ __align__(16) __half smB[2][BN * PADK];

    const int z = blockIdx.z;
    const __half* A = (z == 0) ? A0 : (z == 1) ? A1 : A2;
    const __half* W = (z == 0) ? W0 : (z == 1) ? W1 : W2;
    const float* bias = (z == 0) ? b0p : (z == 1) ? b1p : b2p;
    __half* C = (z == 0) ? C0 : (z == 1) ? C1 : C2;

    const int tid  = threadIdx.x;
    const int wid  = tid >> 5;
    const int lane = tid & 31;
    const int wm   = wid & 3;
    const int wn   = wid >> 2;
    const int m0   = blockIdx.y * BM;
    const int n0   = blockIdx.x * BN;

    const int crow = tid >> 1;
    const int cs0  = (tid & 1) * 2;

    float acc[2][8][4];
#pragma unroll
    for (int i = 0; i < 2; i++)
#pragma unroll
        for (int j = 0; j < 8; j++)
#pragma unroll
            for (int k = 0; k < 4; k++) acc[i][j][k] = 0.0f;

    const uint32_t smA0 = smem_u32(&smA[0][0]);
    const uint32_t smB0 = smem_u32(&smB[0][0]);

    auto issue_copy = [&](int it, int st) {
        const int kb = it * BKC;
        const __half* Ab = A + (size_t)(m0 + crow) * GK + kb;
        const __half* Bb = W + (size_t)(n0 + crow) * GK + kb;
        const uint32_t sa = smA0 + (st * BM * PADK + crow * PADK) * 2;
        const uint32_t sb = smB0 + (st * BN * PADK + crow * PADK) * 2;
#pragma unroll
        for (int s = 0; s < 2; s++) {
            cp_async16(sa + (cs0 + s) * 16, Ab + (cs0 + s) * 8);
            cp_async16(sb + (cs0 + s) * 16, Bb + (cs0 + s) * 8);
        }
        CP_COMMIT();
    };

    issue_copy(0, 0);

    const int NIT1 = GK / BKC;
    for (int it = 0; it < NIT1; it++) {
        const int st = it & 1;
        if (it + 1 < NIT1) {
            issue_copy(it + 1, st ^ 1);
            CP_WAIT(1);
        } else {
            CP_WAIT(0);
        }
        __syncthreads();

        const uint32_t baseA = smA0 + st * BM * PADK * 2;
        const uint32_t baseB = smB0 + st * BN * PADK * 2;
        const int lr = lane & 15;
        const int lc = (lane >> 4) * 8;
#pragma unroll
        for (int ks = 0; ks < 2; ks++) {
            uint32_t a[2][4], b[4][4];
#pragma unroll
            for (int am = 0; am < 2; am++) {
                const int row = wm * 32 + am * 16 + lr;
                ldmx4(a[am], baseA + (row * PADK + ks * 16 + lc) * 2);
            }
#pragma unroll
            for (int bn = 0; bn < 4; bn++) {
                const int row = wn * 64 + bn * 16 + lr;
                ldmx4(b[bn], baseB + (row * PADK + ks * 16 + lc) * 2);
            }
#pragma unroll
            for (int am = 0; am < 2; am++)
#pragma unroll
                for (int bn = 0; bn < 4; bn++) {
                    mma_fp(acc[am][2 * bn + 0], a[am], b[bn][0], b[bn][2]);
                    mma_fp(acc[am][2 * bn + 1], a[am], b[bn][1], b[bn][3]);
                }
        }
        __syncthreads();
    }

    const int er = lane >> 2;
    const int ec = (lane & 3) * 2;
#pragma unroll
    for (int am = 0; am < 2; am++) {
        const int row = m0 + wm * 32 + am * 16 + er;
#pragma unroll
        for (int bn = 0; bn < 8; bn++) {
            const int col = n0 + wn * 64 + bn * 8 + ec;
            const float bx = bias[col], by = bias[col + 1];
            *(half2*)(C + (size_t)row * GN + col) =
                __floats2half2_rn(acc[am][bn][0] + bx, acc[am][bn][1] + by);
            *(half2*)(C + (size_t)(row + 8) * GN + col) =
                __floats2half2_rn(acc[am][bn][2] + bx, acc[am][bn][3] + by);
        }
    }
}

// ============================================================================
// O projection: 2-pass fp16 weight-split GEMM.
//   acc = A @ Wl' (32 iters), acc *= 2^-10, acc += A @ Wh (32 iters), + bias.
//   A = fp16 ctx (single copy). Output fp32.
// ============================================================================
__global__ __launch_bounds__(256, 2) void gemm_o_fp16(
    const __half* __restrict__ A, const __half* __restrict__ Wlo,
    const __half* __restrict__ Whi, const float* __restrict__ bias,
    float* __restrict__ C)
{
    __shared__ __align__(16) __half smA[2][BM * PADK];
    __shared__ __align__(16) __half smB[2][BN * PADK];

    const int tid  = threadIdx.x;
    const int wid  = tid >> 5;
    const int lane = tid & 31;
    const int wm   = wid & 3;
    const int wn   = wid >> 2;
    const int m0   = blockIdx.y * BM;
    const int n0   = blockIdx.x * BN;

    const int crow = tid >> 1;
    const int cs0  = (tid & 1) * 2;

    float acc[2][8][4];
#pragma unroll
    for (int i = 0; i < 2; i++)
#pragma unroll
        for (int j = 0; j < 8; j++)
#pragma unroll
            for (int k = 0; k < 4; k++) acc[i][j][k] = 0.0f;

    const uint32_t smA0 = smem_u32(&smA[0][0]);
    const uint32_t smB0 = smem_u32(&smB[0][0]);

    const int HALF_IT = GK / BKC;        // 32
    const int NIT2 = 2 * HALF_IT;        // 64

    auto issue_copy = [&](int it, int st) {
        const __half* Wp = (it < HALF_IT) ? Wlo : Whi;
        const int kb = (it & (HALF_IT - 1)) * BKC;
        const __half* Ab = A + (size_t)(m0 + crow) * GK + kb;
        const __half* Bb = Wp + (size_t)(n0 + crow) * GK + kb;
        const uint32_t sa = smA0 + (st * BM * PADK + crow * PADK) * 2;
        const uint32_t sb = smB0 + (st * BN * PADK + crow * PADK) * 2;
#pragma unroll
        for (int s = 0; s < 2; s++) {
            cp_async16(sa + (cs0 + s) * 16, Ab + (cs0 + s) * 8);
            cp_async16(sb + (cs0 + s) * 16, Bb + (cs0 + s) * 8);
        }
        CP_COMMIT();
    };

    issue_copy(0, 0);

    for (int it = 0; it < NIT2; it++) {
        const int st = it & 1;
        if (it + 1 < NIT2) {
            issue_copy(it + 1, st ^ 1);
            CP_WAIT(1);
        } else {
            CP_WAIT(0);
        }
        __syncthreads();

        const uint32_t baseA = smA0 + st * BM * PADK * 2;
        const uint32_t baseB = smB0 + st * BN * PADK * 2;
        const int lr = lane & 15;
        const int lc = (lane >> 4) * 8;
#pragma unroll
        for (int ks = 0; ks < 2; ks++) {
            uint32_t a[2][4], b[4][4];
#pragma unroll
            for (int am = 0; am < 2; am++) {
                const int row = wm * 32 + am * 16 + lr;
                ldmx4(a[am], baseA + (row * PADK + ks * 16 + lc) * 2);
            }
#pragma unroll
            for (int bn = 0; bn < 4; bn++) {
                const int row = wn * 64 + bn * 16 + lr;
                ldmx4(b[bn], baseB + (row * PADK + ks * 16 + lc) * 2);
            }
#pragma unroll
            for (int am = 0; am < 2; am++)
#pragma unroll
                for (int bn = 0; bn < 4; bn++) {
                    mma_fp(acc[am][2 * bn + 0], a[am], b[bn][0], b[bn][2]);
                    mma_fp(acc[am][2 * bn + 1], a[am], b[bn][1], b[bn][3]);
                }
        }
        if (it == HALF_IT - 1) {      // lo pass done: undo the 2^10 pre-scale
#pragma unroll
            for (int i = 0; i < 2; i++)
#pragma unroll
                for (int j = 0; j < 8; j++)
#pragma unroll
                    for (int k = 0; k < 4; k++) acc[i][j][k] *= 0.0009765625f;
        }
        __syncthreads();
    }

    const int er = lane >> 2;
    const int ec = (lane & 3) * 2;
#pragma unroll
    for (int am = 0; am < 2; am++) {
        const int row = m0 + wm * 32 + am * 16 + er;
#pragma unroll
        for (int bn = 0; bn < 8; bn++) {
            const int col = n0 + wn * 64 + bn * 8 + ec;
            const float bx = bias[col], by = bias[col + 1];
            *(float2*)(C + (size_t)row * GN + col) =
                make_float2(acc[am][bn][0] + bx, acc[am][bn][1] + by);
            *(float2*)(C + (size_t)(row + 8) * GN + col) =
                make_float2(acc[am][bn][2] + bx, acc[am][bn][3] + by);
        }
    }
}

// ============================================================================
// Fused flash attention, fp16 mma.sync, BKV=128, register-resident P.
//   8 warps x 16 q-rows, K/V double-buffered cp.async, 1 CTA/SM (regs > 128).
//   ctx written as fp16.
// ============================================================================
#define BQ 128
#define BKV 128
#define QS 72
#define NTKV (SQ / BKV)   // 16
#define ATTN_SMEM ((BQ * QS + 4 * BKV * QS) * 2)   // 92160 B

__global__ __launch_bounds__(256, 1) void attn_mma(
    const __half* __restrict__ Qh, const __half* __restrict__ Kh,
    const __half* __restrict__ Vh, __half* __restrict__ Ctx)
{
    extern __shared__ __half sm[];
    __half* sQ = sm;                   // [128][QS]
    __half* sK = sQ + BQ * QS;         // [2][128][QS]
    __half* sV = sK + 2 * BKV * QS;    // [2][128][QS]

    const int tid  = threadIdx.x;
    const int wid  = tid >> 5;
    const int lane = tid & 31;
    const int lr   = lane & 15;
    const int lc   = (lane >> 4) * 8;
    const int er   = lane >> 2;
    const int ec   = (lane & 3) * 2;
    const int wrow = wid * 16;

    const int q0 = blockIdx.x * BQ;
    const size_t hb = ((size_t)blockIdx.z * SQ) * (size_t)GN + (size_t)blockIdx.y * DKH;

    const uint32_t sQb = smem_u32(sQ);
    const uint32_t sKb = smem_u32(sK);
    const uint32_t sVb = smem_u32(sV);

    // K/V copy mapping: 128 rows, 2 threads/row, 4x16B segments each
    const int crow = tid >> 1;
    const int cs0  = (tid & 1) * 4;

    auto loadKV = [&](int kt, int st) {
        const __half* kp = Kh + hb + (size_t)(kt * BKV + crow) * GN;
        const __half* vp = Vh + hb + (size_t)(kt * BKV + crow) * GN;
        const uint32_t dk = sKb + (st * BKV * QS + crow * QS) * 2;
        const uint32_t dv = sVb + (st * BKV * QS + crow * QS) * 2;
#pragma unroll
        for (int s = 0; s < 4; s++) {
            cp_async16(dk + (cs0 + s) * 16, kp + (cs0 + s) * 8);
            cp_async16(dv + (cs0 + s) * 16, vp + (cs0 + s) * 8);
        }
    };

    {
        const __half* qp = Qh + hb + (size_t)(q0 + crow) * GN;
        const uint32_t dq = sQb + (crow * QS) * 2;
#pragma unroll
        for (int s = 0; s < 4; s++)
            cp_async16(dq + (cs0 + s) * 16, qp + (cs0 + s) * 8);
    }
    loadKV(0, 0);
    CP_COMMIT();
    loadKV(1, 1);
    CP_COMMIT();

    float m0r = -1.0e30f, m1r = -1.0e30f, l0 = 0.0f, l1 = 0.0f;
    float o[8][4];
#pragma unroll
    for (int j = 0; j < 8; j++)
#pragma unroll
        for (int k = 0; k < 4; k++) o[j][k] = 0.0f;

    uint32_t aq[4][4];   // Q fragments, loaded once

    for (int kt = 0; kt < NTKV; kt++) {
        if (kt < NTKV - 1) { CP_WAIT(1); } else { CP_WAIT(0); }
        __syncthreads();
        if (kt == 0) {
#pragma unroll
            for (int ks = 0; ks < 4; ks++)
                ldmx4(aq[ks], sQb + ((wrow + lr) * QS + ks * 16 + lc) * 2);
        }
        const int st = kt & 1;
        const uint32_t kbase = sKb + st * BKV * QS * 2;
        const uint32_t vbase = sVb + st * BKV * QS * 2;

        // ---- S = Q K^T (16 x 128 per warp) ----
        float s[16][4];
#pragma unroll
        for (int t = 0; t < 16; t++)
#pragma unroll
            for (int k = 0; k < 4; k++) s[t][k] = 0.0f;

#pragma unroll
        for (int ks = 0; ks < 4; ks++) {
#pragma unroll
            for (int nt = 0; nt < 8; nt++) {
                uint32_t b[4];
                ldmx4(b, kbase + ((nt * 16 + lr) * QS + ks * 16 + lc) * 2);
                mma_fp(s[2 * nt + 0], aq[ks], b[0], b[2]);
                mma_fp(s[2 * nt + 1], aq[ks], b[1], b[3]);
            }
        }

        // ---- online softmax; P packed into A-frag registers ----
        float mx0 = -1.0e30f, mx1 = -1.0e30f;
#pragma unroll
        for (int t = 0; t < 16; t++) {
            mx0 = fmaxf(mx0, fmaxf(s[t][0], s[t][1]));
            mx1 = fmaxf(mx1, fmaxf(s[t][2], s[t][3]));
        }
        mx0 = fmaxf(mx0, __shfl_xor_sync(0xffffffffu, mx0, 1));
        mx0 = fmaxf(mx0, __shfl_xor_sync(0xffffffffu, mx0, 2));
        mx1 = fmaxf(mx1, __shfl_xor_sync(0xffffffffu, mx1, 1));
        mx1 = fmaxf(mx1, __shfl_xor_sync(0xffffffffu, mx1, 2));
        mx0 *= 0.125f;
        mx1 *= 0.125f;
        const float mn0 = fmaxf(m0r, mx0);
        const float mn1 = fmaxf(m1r, mx1);
        const float c0 = __expf(m0r - mn0);
        const float c1 = __expf(m1r - mn1);

        float rs0 = 0.0f, rs1 = 0.0f;
        uint32_t pw[16][2];
#pragma unroll
        for (int t = 0; t < 16; t++) {
            const float p00 = __expf(fmaf(s[t][0], 0.125f, -mn0));
            const float p01 = __expf(fmaf(s[t][1], 0.125f, -mn0));
            const float p10 = __expf(fmaf(s[t][2], 0.125f, -mn1));
            const float p11 = __expf(fmaf(s[t][3], 0.125f, -mn1));
            rs0 += p00 + p01;
            rs1 += p10 + p11;
            pw[t][0] = pack_h2(p00, p01);
            pw[t][1] = pack_h2(p10, p11);
        }
        rs0 += __shfl_xor_sync(0xffffffffu, rs0, 1);
        rs0 += __shfl_xor_sync(0xffffffffu, rs0, 2);
        rs1 += __shfl_xor_sync(0xffffffffu, rs1, 1);
        rs1 += __shfl_xor_sync(0xffffffffu, rs1, 2);
        l0 = l0 * c0 + rs0;
        l1 = l1 * c1 + rs1;
        m0r = mn0;
        m1r = mn1;
#pragma unroll
        for (int j = 0; j < 8; j++) {
            o[j][0] *= c0; o[j][1] *= c0;
            o[j][2] *= c1; o[j][3] *= c1;
        }

        // ---- O += P V (P from registers, V via ldmatrix.trans) ----
#pragma unroll
        for (int j = 0; j < 8; j++) {      // 16-key chunks
            const uint32_t pa[4] = {pw[2 * j][0], pw[2 * j][1],
                                    pw[2 * j + 1][0], pw[2 * j + 1][1]};
#pragma unroll
            for (int dt = 0; dt < 4; dt++) {
                uint32_t vb[4];
                ldmx4t(vb, vbase + ((j * 16 + lr) * QS + dt * 16 + lc) * 2);
                mma_fp(o[2 * dt + 0], pa, vb[0], vb[1]);
                mma_fp(o[2 * dt + 1], pa, vb[2], vb[3]);
            }
        }
        __syncthreads();   // all warps done with stage st before refill
        if (kt + 2 < NTKV) {
            loadKV(kt + 2, st);
            CP_COMMIT();
        }
    }

    // ---- normalize + write ctx (fp16, [B,S,h*64+d]) ----
    const float inv0 = 1.0f / l0;
    const float inv1 = 1.0f / l1;
    const int row0 = q0 + wrow + er;
#pragma unroll
    for (int j = 0; j < 8; j++) {
        const int col = j * 8 + ec;
        __half* p0 = Ctx + hb + (size_t)row0 * GN + col;
        __half* p1 = Ctx + hb + (size_t)(row0 + 8) * GN + col;
        *(half2*)p0 = __floats2half2_rn(o[j][0] * inv0, o[j][1] * inv0);
        *(half2*)p1 = __floats2half2_rn(o[j][2] * inv1, o[j][3] * inv1);
    }
}

// ============================================================================
// Launch
// ============================================================================
extern "C" void kernel_launch(void* const* d_in, const int* in_sizes, int n_in,
                              void* d_out, int out_size)
{
    const float* q  = (const float*)d_in[0];
    const float* k  = (const float*)d_in[1];
    const float* v  = (const float*)d_in[2];
    const float* Wq = (const float*)d_in[3];
    const float* bq = (const float*)d_in[4];
    const float* Wk = (const float*)d_in[5];
    const float* bk = (const float*)d_in[6];
    const float* Wv = (const float*)d_in[7];
    const float* bv = (const float*)d_in[8];
    const float* Wo = (const float*)d_in[9];
    const float* bo = (const float*)d_in[10];
    float* out = (float*)d_out;

    __half *hQ, *hK, *hV, *hC, *a16, *w16, *woh, *wol;
    cudaGetSymbolAddress((void**)&hQ, g_hQ);
    cudaGetSymbolAddress((void**)&hK, g_hK);
    cudaGetSymbolAddress((void**)&hV, g_hV);
    cudaGetSymbolAddress((void**)&hC, g_hC);
    cudaGetSymbolAddress((void**)&a16, g_a16);
    cudaGetSymbolAddress((void**)&w16, g_w16);
    cudaGetSymbolAddress((void**)&woh, g_woh);
    cudaGetSymbolAddress((void**)&wol, g_wol);

    __half* a0 = a16;
    __half* a1 = a16 + (size_t)GM * GK;
    __half* a2 = a16 + 2 * (size_t)GM * GK;
    __half* w0 = w16;
    __half* w1 = w16 + (size_t)GN * GK;
    __half* w2 = w16 + 2 * (size_t)GN * GK;

    const int n4_act = GM * GK / 4;
    const int n4_w   = GN * GK / 4;

    conv_fp16_x3<<<dim3(n4_act / 256, 3), 256>>>(
        (const float4*)q, (const float4*)k, (const float4*)v,
        (half2*)a0, (half2*)a1, (half2*)a2, n4_act);
    conv_fp16_x3<<<dim3(n4_w / 256, 3), 256>>>(
        (const float4*)Wq, (const float4*)Wk, (const float4*)Wv,
        (half2*)w0, (half2*)w1, (half2*)w2, n4_w);
    split_fp16w<<<n4_w / 256, 256>>>((const float4*)Wo,
        (half2*)woh, (half2*)wol, n4_w);

    gemm_qkv_fp16<<<dim3(GN / BN, GM / BM, 3), 256>>>(
        a0, a1, a2, w0, w1, w2, bq, bk, bv, hQ, hK, hV);

    cudaFuncSetAttribute(attn_mma, cudaFuncAttributeMaxDynamicSharedMemorySize, ATTN_SMEM);
    attn_mma<<<dim3(SQ / BQ, NH, NB), 256, ATTN_SMEM>>>(hQ, hK, hV, hC);

    gemm_o_fp16<<<dim3(GN / BN, GM / BM), 256>>>(hC, wol, woh, bo, out);
}

// round 10
// speedup vs baseline: 1.6854x; 1.0267x over previous
#include <cuda_runtime.h>
#include <cuda_fp16.h>
#include <cuda_bf16.h>
#include <cstdint>
#include <math.h>

// Problem constants
#define GM 8192      // B*S
#define GN 1024      // D_MODEL
#define GK 1024      // D_MODEL
#define SQ 2048      // S
#define NB 4         // B
#define NH 16        // heads
#define DKH 64       // d_k per head

// Scratch (allocation-free rule: __device__ globals)
__device__ __half g_hQ[(size_t)GM * GN];
__device__ __half g_hK[(size_t)GM * GN];
__device__ __half g_hV[(size_t)GM * GN];
__device__ __half g_hC[(size_t)GM * GN];      // fp16 ctx
// fp16 inputs for single-pass Q/K/V projections
__device__ __half g_a16[3][(size_t)GM * GK];
__device__ __half g_w16[3][(size_t)GN * GK];
// fp16 hi/lo split of Wo (lo pre-scaled by 2^10)
__device__ __half g_woh[(size_t)GN * GK];
__device__ __half g_wol[(size_t)GN * GK];

__device__ __forceinline__ uint32_t smem_u32(const void* p) {
    uint32_t a;
    asm("{ .reg .u64 t; cvta.to.shared.u64 t, %1; cvt.u32.u64 %0, t; }"
        : "=r"(a) : "l"(p));
    return a;
}

__device__ __forceinline__ void cp_async16(uint32_t sm, const void* g) {
    asm volatile("cp.async.cg.shared.global [%0], [%1], 16;\n"
                 :: "r"(sm), "l"(g));
}
#define CP_COMMIT() asm volatile("cp.async.commit_group;\n" ::: "memory")
#define CP_WAIT(N)  asm volatile("cp.async.wait_group %0;\n" :: "n"(N) : "memory")

__device__ __forceinline__ void ldmx4(uint32_t* r, uint32_t addr) {
    asm volatile("ldmatrix.sync.aligned.m8n8.x4.shared.b16 {%0,%1,%2,%3}, [%4];"
                 : "=r"(r[0]), "=r"(r[1]), "=r"(r[2]), "=r"(r[3]) : "r"(addr));
}
__device__ __forceinline__ void ldmx4t(uint32_t* r, uint32_t addr) {
    asm volatile("ldmatrix.sync.aligned.m8n8.x4.trans.shared.b16 {%0,%1,%2,%3}, [%4];"
                 : "=r"(r[0]), "=r"(r[1]), "=r"(r[2]), "=r"(r[3]) : "r"(addr));
}

__device__ __forceinline__ void mma_fp(float* c, const uint32_t* a,
                                       uint32_t b0, uint32_t b1) {
    asm volatile(
        "mma.sync.aligned.m16n8k16.row.col.f32.f16.f16.f32 "
        "{%0,%1,%2,%3}, {%4,%5,%6,%7}, {%8,%9}, {%0,%1,%2,%3};"
        : "+f"(c[0]), "+f"(c[1]), "+f"(c[2]), "+f"(c[3])
        : "r"(a[0]), "r"(a[1]), "r"(a[2]), "r"(a[3]), "r"(b0), "r"(b1));
}

__device__ __forceinline__ uint32_t pack_h2(float x, float y) {
    const half2 h = __floats2half2_rn(x, y);
    return *reinterpret_cast<const uint32_t*>(&h);
}

// ============================================================================
// fp32 -> fp16 convert, 3 tensors per launch (z selects)
// ============================================================================
__global__ __launch_bounds__(256) void conv_fp16_x3(
    const float4* __restrict__ s0, const float4* __restrict__ s1,
    const float4* __restrict__ s2, half2* __restrict__ d0,
    half2* __restrict__ d1, half2* __restrict__ d2, int n4)
{
    const int z = blockIdx.y;
    const float4* src = (z == 0) ? s0 : (z == 1) ? s1 : s2;
    half2* dst = (z == 0) ? d0 : (z == 1) ? d1 : d2;
    const int i = blockIdx.x * 256 + threadIdx.x;
    if (i >= n4) return;
    const float4 v = src[i];
    dst[2 * i]     = __floats2half2_rn(v.x, v.y);
    dst[2 * i + 1] = __floats2half2_rn(v.z, v.w);
}

// ============================================================================
// fp32 -> fp16 (hi, lo*2^10) split, for Wo
// ============================================================================
__global__ __launch_bounds__(256) void split_fp16w(
    const float4* __restrict__ src, half2* __restrict__ hi,
    half2* __restrict__ lo, int n4)
{
    const int i = blockIdx.x * 256 + threadIdx.x;
    if (i >= n4) return;
    const float4 v = src[i];
    const __half h0 = __float2half_rn(v.x);
    const __half h1 = __float2half_rn(v.y);
    const __half h2 = __float2half_rn(v.z);
    const __half h3 = __float2half_rn(v.w);
    hi[2 * i]     = __halves2half2(h0, h1);
    hi[2 * i + 1] = __halves2half2(h2, h3);
    lo[2 * i]     = __floats2half2_rn((v.x - __half2float(h0)) * 1024.0f,
                                      (v.y - __half2float(h1)) * 1024.0f);
    lo[2 * i + 1] = __floats2half2_rn((v.z - __half2float(h2)) * 1024.0f,
                                      (v.w - __half2float(h3)) * 1024.0f);
}

#define BM 128
#define BN 128
#define BKC 32
#define PADK 40
#define GEMM_STAGE_HALVES ((BM + BN) * PADK)          // 10240 halves/stage
#define GEMM_SMEM (3 * GEMM_STAGE_HALVES * 2)         // 61440 B

// ============================================================================
// Single-pass fp16 GEMM for Q/K/V projections, fused via blockIdx.z.
//   3-stage cp.async pipeline, ONE __syncthreads per iteration.
// ============================================================================
__global__ __launch_bounds__(256, 2) void gemm_qkv_fp16(
    const __half* __restrict__ A0, const __half* __restrict__ A1,
    const __half* __restrict__ A2, const __half* __restrict__ W0,
    const __half* __restrict__ W1, const __half* __restrict__ W2,
    const float* __restrict__ b0p, const float* __restrict__ b1p,
    const float* __restrict__ b2p, __half* __restrict__ C0,
    __half* __restrict__ C1, __half* __restrict__ C2)
{
    extern __shared__ __half dynsm[];
    __half* smA = dynsm;                         // [3][BM*PADK]
    __half* smB = dynsm + 3 * BM * PADK;         // [3][BN*PADK]

    const int z = blockIdx.z;
    const __half* A = (z == 0) ? A0 : (z == 1) ? A1 : A2;
    const __half* W = (z == 0) ? W0 : (z == 1) ? W1 : W2;
    const float* bias = (z == 0) ? b0p : (z == 1) ? b1p : b2p;
    __half* C = (z == 0) ? C0 : (z == 1) ? C1 : C2;

    const int tid  = threadIdx.x;
    const int wid  = tid >> 5;
    const int lane = tid & 31;
    const int wm   = wid & 3;
    const int wn   = wid >> 2;
    const int m0   = blockIdx.y * BM;
    const int n0   = blockIdx.x * BN;

    const int crow = tid >> 1;
    const int cs0  = (tid & 1) * 2;
    const int lr = lane & 15;
    const int lc = (lane >> 4) * 8;

    float acc[2][8][4];
#pragma unroll
    for (int i = 0; i < 2; i++)
#pragma unroll
        for (int j = 0; j < 8; j++)
#pragma unroll
            for (int k = 0; k < 4; k++) acc[i][j][k] = 0.0f;

    const uint32_t smA0 = smem_u32(smA);
    const uint32_t smB0 = smem_u32(smB);

    auto issue_copy = [&](int it, int st) {
        const int kb = it * BKC;
        const __half* Ab = A + (size_t)(m0 + crow) * GK + kb;
        const __half* Bb = W + (size_t)(n0 + crow) * GK + kb;
        const uint32_t sa = smA0 + (st * BM * PADK + crow * PADK) * 2;
        const uint32_t sb = smB0 + (st * BN * PADK + crow * PADK) * 2;
#pragma unroll
        for (int s = 0; s < 2; s++) {
            cp_async16(sa + (cs0 + s) * 16, Ab + (cs0 + s) * 8);
            cp_async16(sb + (cs0 + s) * 16, Bb + (cs0 + s) * 8);
        }
        CP_COMMIT();
    };

    const int NIT1 = GK / BKC;   // 32
    issue_copy(0, 0);
    issue_copy(1, 1);

    for (int it = 0; it < NIT1; it++) {
        const int st = it % 3;
        if (it + 1 < NIT1) { CP_WAIT(1); } else { CP_WAIT(0); }
        __syncthreads();

        const uint32_t baseA = smA0 + st * BM * PADK * 2;
        const uint32_t baseB = smB0 + st * BN * PADK * 2;
#pragma unroll
        for (int ks = 0; ks < 2; ks++) {
            uint32_t a[2][4], b[4][4];
#pragma unroll
            for (int am = 0; am < 2; am++) {
                const int row = wm * 32 + am * 16 + lr;
                ldmx4(a[am], baseA + (row * PADK + ks * 16 + lc) * 2);
            }
#pragma unroll
            for (int bn = 0; bn < 4; bn++) {
                const int row = wn * 64 + bn * 16 + lr;
                ldmx4(b[bn], baseB + (row * PADK + ks * 16 + lc) * 2);
            }
#pragma unroll
            for (int am = 0; am < 2; am++)
#pragma unroll
                for (int bn = 0; bn < 4; bn++) {
                    mma_fp(acc[am][2 * bn + 0], a[am], b[bn][0], b[bn][2]);
                    mma_fp(acc[am][2 * bn + 1], a[am], b[bn][1], b[bn][3]);
                }
        }
        if (it + 2 < NIT1) issue_copy(it + 2, (it + 2) % 3);
    }

    const int er = lane >> 2;
    const int ec = (lane & 3) * 2;
#pragma unroll
    for (int am = 0; am < 2; am++) {
        const int row = m0 + wm * 32 + am * 16 + er;
#pragma unroll
        for (int bn = 0; bn < 8; bn++) {
            const int col = n0 + wn * 64 + bn * 8 + ec;
            const float bx = bias[col], by = bias[col + 1];
            *(half2*)(C + (size_t)row * GN + col) =
                __floats2half2_rn(acc[am][bn][0] + bx, acc[am][bn][1] + by);
            *(half2*)(C + (size_t)(row + 8) * GN + col) =
                __floats2half2_rn(acc[am][bn][2] + bx, acc[am][bn][3] + by);
        }
    }
}

// ============================================================================
// O projection: 2-pass fp16 weight-split GEMM, 3-stage pipeline, 1 sync/iter.
//   acc = A @ Wl' (32 iters), acc *= 2^-10, acc += A @ Wh (32 iters), + bias.
// ============================================================================
__global__ __launch_bounds__(256, 2) void gemm_o_fp16(
    const __half* __restrict__ A, const __half* __restrict__ Wlo,
    const __half* __restrict__ Whi, const float* __restrict__ bias,
    float* __restrict__ C)
{
    extern __shared__ __half dynsm[];
    __half* smA = dynsm;
    __half* smB = dynsm + 3 * BM * PADK;

    const int tid  = threadIdx.x;
    const int wid  = tid >> 5;
    const int lane = tid & 31;
    const int wm   = wid & 3;
    const int wn   = wid >> 2;
    const int m0   = blockIdx.y * BM;
    const int n0   = blockIdx.x * BN;

    const int crow = tid >> 1;
    const int cs0  = (tid & 1) * 2;
    const int lr = lane & 15;
    const int lc = (lane >> 4) * 8;

    float acc[2][8][4];
#pragma unroll
    for (int i = 0; i < 2; i++)
#pragma unroll
        for (int j = 0; j < 8; j++)
#pragma unroll
            for (int k = 0; k < 4; k++) acc[i][j][k] = 0.0f;

    const uint32_t smA0 = smem_u32(smA);
    const uint32_t smB0 = smem_u32(smB);

    const int HALF_IT = GK / BKC;        // 32
    const int NIT2 = 2 * HALF_IT;        // 64

    auto issue_copy = [&](int it, int st) {
        const __half* Wp = (it < HALF_IT) ? Wlo : Whi;
        const int kb = (it & (HALF_IT - 1)) * BKC;
        const __half* Ab = A + (size_t)(m0 + crow) * GK + kb;
        const __half* Bb = Wp + (size_t)(n0 + crow) * GK + kb;
        const uint32_t sa = smA0 + (st * BM * PADK + crow * PADK) * 2;
        const uint32_t sb = smB0 + (st * BN * PADK + crow * PADK) * 2;
#pragma unroll
        for (int s = 0; s < 2; s++) {
            cp_async16(sa + (cs0 + s) * 16, Ab + (cs0 + s) * 8);
            cp_async16(sb + (cs0 + s) * 16, Bb + (cs0 + s) * 8);
        }
        CP_COMMIT();
    };

    issue_copy(0, 0);
    issue_copy(1, 1);

    for (int it = 0; it < NIT2; it++) {
        const int st = it % 3;
        if (it + 1 < NIT2) { CP_WAIT(1); } else { CP_WAIT(0); }
        __syncthreads();

        const uint32_t baseA = smA0 + st * BM * PADK * 2;
        const uint32_t baseB = smB0 + st * BN * PADK * 2;
#pragma unroll
        for (int ks = 0; ks < 2; ks++) {
            uint32_t a[2][4], b[4][4];
#pragma unroll
            for (int am = 0; am < 2; am++) {
                const int row = wm * 32 + am * 16 + lr;
                ldmx4(a[am], baseA + (row * PADK + ks * 16 + lc) * 2);
            }
#pragma unroll
            for (int bn = 0; bn < 4; bn++) {
                const int row = wn * 64 + bn * 16 + lr;
                ldmx4(b[bn], baseB + (row * PADK + ks * 16 + lc) * 2);
            }
#pragma unroll
            for (int am = 0; am < 2; am++)
#pragma unroll
                for (int bn = 0; bn < 4; bn++) {
                    mma_fp(acc[am][2 * bn + 0], a[am], b[bn][0], b[bn][2]);
                    mma_fp(acc[am][2 * bn + 1], a[am], b[bn][1], b[bn][3]);
                }
        }
        if (it == HALF_IT - 1) {      // lo pass done: undo the 2^10 pre-scale
#pragma unroll
            for (int i = 0; i < 2; i++)
#pragma unroll
                for (int j = 0; j < 8; j++)
#pragma unroll
                    for (int k = 0; k < 4; k++) acc[i][j][k] *= 0.0009765625f;
        }
        if (it + 2 < NIT2) issue_copy(it + 2, (it + 2) % 3);
    }

    const int er = lane >> 2;
    const int ec = (lane & 3) * 2;
#pragma unroll
    for (int am = 0; am < 2; am++) {
        const int row = m0 + wm * 32 + am * 16 + er;
#pragma unroll
        for (int bn = 0; bn < 8; bn++) {
            const int col = n0 + wn * 64 + bn * 8 + ec;
            const float bx = bias[col], by = bias[col + 1];
            *(float2*)(C + (size_t)row * GN + col) =
                make_float2(acc[am][bn][0] + bx, acc[am][bn][1] + by);
            *(float2*)(C + (size_t)(row + 8) * GN + col) =
                make_float2(acc[am][bn][2] + bx, acc[am][bn][3] + by);
        }
    }
}

// ============================================================================
// Fused flash attention, fp16 mma.sync, BKV=128, register-resident P.
//   Unchanged from R8 (passing, 1 CTA/SM).
// ============================================================================
#define BQ 128
#define BKV 128
#define QS 72
#define NTKV (SQ / BKV)   // 16
#define ATTN_SMEM ((BQ * QS + 4 * BKV * QS) * 2)   // 92160 B

__global__ __launch_bounds__(256, 1) void attn_mma(
    const __half* __restrict__ Qh, const __half* __restrict__ Kh,
    const __half* __restrict__ Vh, __half* __restrict__ Ctx)
{
    extern __shared__ __half sm[];
    __half* sQ = sm;                   // [128][QS]
    __half* sK = sQ + BQ * QS;         // [2][128][QS]
    __half* sV = sK + 2 * BKV * QS;    // [2][128][QS]

    const int tid  = threadIdx.x;
    const int wid  = tid >> 5;
    const int lane = tid & 31;
    const int lr   = lane & 15;
    const int lc   = (lane >> 4) * 8;
    const int er   = lane >> 2;
    const int ec   = (lane & 3) * 2;
    const int wrow = wid * 16;

    const int q0 = blockIdx.x * BQ;
    const size_t hb = ((size_t)blockIdx.z * SQ) * (size_t)GN + (size_t)blockIdx.y * DKH;

    const uint32_t sQb = smem_u32(sQ);
    const uint32_t sKb = smem_u32(sK);
    const uint32_t sVb = smem_u32(sV);

    const int crow = tid >> 1;
    const int cs0  = (tid & 1) * 4;

    auto loadKV = [&](int kt, int st) {
        const __half* kp = Kh + hb + (size_t)(kt * BKV + crow) * GN;
        const __half* vp = Vh + hb + (size_t)(kt * BKV + crow) * GN;
        const uint32_t dk = sKb + (st * BKV * QS + crow * QS) * 2;
        const uint32_t dv = sVb + (st * BKV * QS + crow * QS) * 2;
#pragma unroll
        for (int s = 0; s < 4; s++) {
            cp_async16(dk + (cs0 + s) * 16, kp + (cs0 + s) * 8);
            cp_async16(dv + (cs0 + s) * 16, vp + (cs0 + s) * 8);
        }
    };

    {
        const __half* qp = Qh + hb + (size_t)(q0 + crow) * GN;
        const uint32_t dq = sQb + (crow * QS) * 2;
#pragma unroll
        for (int s = 0; s < 4; s++)
            cp_async16(dq + (cs0 + s) * 16, qp + (cs0 + s) * 8);
    }
    loadKV(0, 0);
    CP_COMMIT();
    loadKV(1, 1);
    CP_COMMIT();

    float m0r = -1.0e30f, m1r = -1.0e30f, l0 = 0.0f, l1 = 0.0f;
    float o[8][4];
#pragma unroll
    for (int j = 0; j < 8; j++)
#pragma unroll
        for (int k = 0; k < 4; k++) o[j][k] = 0.0f;

    uint32_t aq[4][4];   // Q fragments, loaded once

    for (int kt = 0; kt < NTKV; kt++) {
        if (kt < NTKV - 1) { CP_WAIT(1); } else { CP_WAIT(0); }
        __syncthreads();
        if (kt == 0) {
#pragma unroll
            for (int ks = 0; ks < 4; ks++)
                ldmx4(aq[ks], sQb + ((wrow + lr) * QS + ks * 16 + lc) * 2);
        }
        const int st = kt & 1;
        const uint32_t kbase = sKb + st * BKV * QS * 2;
        const uint32_t vbase = sVb + st * BKV * QS * 2;

        // ---- S = Q K^T (16 x 128 per warp) ----
        float s[16][4];
#pragma unroll
        for (int t = 0; t < 16; t++)
#pragma unroll
            for (int k = 0; k < 4; k++) s[t][k] = 0.0f;

#pragma unroll
        for (int ks = 0; ks < 4; ks++) {
#pragma unroll
            for (int nt = 0; nt < 8; nt++) {
                uint32_t b[4];
                ldmx4(b, kbase + ((nt * 16 + lr) * QS + ks * 16 + lc) * 2);
                mma_fp(s[2 * nt + 0], aq[ks], b[0], b[2]);
                mma_fp(s[2 * nt + 1], aq[ks], b[1], b[3]);
            }
        }

        // ---- online softmax; P packed into A-frag registers ----
        float mx0 = -1.0e30f, mx1 = -1.0e30f;
#pragma unroll
        for (int t = 0; t < 16; t++) {
            mx0 = fmaxf(mx0, fmaxf(s[t][0], s[t][1]));
            mx1 = fmaxf(mx1, fmaxf(s[t][2], s[t][3]));
        }
        mx0 = fmaxf(mx0, __shfl_xor_sync(0xffffffffu, mx0, 1));
        mx0 = fmaxf(mx0, __shfl_xor_sync(0xffffffffu, mx0, 2));
        mx1 = fmaxf(mx1, __shfl_xor_sync(0xffffffffu, mx1, 1));
        mx1 = fmaxf(mx1, __shfl_xor_sync(0xffffffffu, mx1, 2));
        mx0 *= 0.125f;
        mx1 *= 0.125f;
        const float mn0 = fmaxf(m0r, mx0);
        const float mn1 = fmaxf(m1r, mx1);
        const float c0 = __expf(m0r - mn0);
        const float c1 = __expf(m1r - mn1);

        float rs0 = 0.0f, rs1 = 0.0f;
        uint32_t pw[16][2];
#pragma unroll
        for (int t = 0; t < 16; t++) {
            const float p00 = __expf(fmaf(s[t][0], 0.125f, -mn0));
            const float p01 = __expf(fmaf(s[t][1], 0.125f, -mn0));
            const float p10 = __expf(fmaf(s[t][2], 0.125f, -mn1));
            const float p11 = __expf(fmaf(s[t][3], 0.125f, -mn1));
            rs0 += p00 + p01;
            rs1 += p10 + p11;
            pw[t][0] = pack_h2(p00, p01);
            pw[t][1] = pack_h2(p10, p11);
        }
        rs0 += __shfl_xor_sync(0xffffffffu, rs0, 1);
        rs0 += __shfl_xor_sync(0xffffffffu, rs0, 2);
        rs1 += __shfl_xor_sync(0xffffffffu, rs1, 1);
        rs1 += __shfl_xor_sync(0xffffffffu, rs1, 2);
        l0 = l0 * c0 + rs0;
        l1 = l1 * c1 + rs1;
        m0r = mn0;
        m1r = mn1;
#pragma unroll
        for (int j = 0; j < 8; j++) {
            o[j][0] *= c0; o[j][1] *= c0;
            o[j][2] *= c1; o[j][3] *= c1;
        }

        // ---- O += P V (P from registers, V via ldmatrix.trans) ----
#pragma unroll
        for (int j = 0; j < 8; j++) {      // 16-key chunks
            const uint32_t pa[4] = {pw[2 * j][0], pw[2 * j][1],
                                    pw[2 * j + 1][0], pw[2 * j + 1][1]};
#pragma unroll
            for (int dt = 0; dt < 4; dt++) {
                uint32_t vb[4];
                ldmx4t(vb, vbase + ((j * 16 + lr) * QS + dt * 16 + lc) * 2);
                mma_fp(o[2 * dt + 0], pa, vb[0], vb[1]);
                mma_fp(o[2 * dt + 1], pa, vb[2], vb[3]);
            }
        }
        __syncthreads();
        if (kt + 2 < NTKV) {
            loadKV(kt + 2, st);
            CP_COMMIT();
        }
    }

    const float inv0 = 1.0f / l0;
    const float inv1 = 1.0f / l1;
    const int row0 = q0 + wrow + er;
#pragma unroll
    for (int j = 0; j < 8; j++) {
        const int col = j * 8 + ec;
        __half* p0 = Ctx + hb + (size_t)row0 * GN + col;
        __half* p1 = Ctx + hb + (size_t)(row0 + 8) * GN + col;
        *(half2*)p0 = __floats2half2_rn(o[j][0] * inv0, o[j][1] * inv0);
        *(half2*)p1 = __floats2half2_rn(o[j][2] * inv1, o[j][3] * inv1);
    }
}

// ============================================================================
// Launch
// ============================================================================
extern "C" void kernel_launch(void* const* d_in, const int* in_sizes, int n_in,
                              void* d_out, int out_size)
{
    const float* q  = (const float*)d_in[0];
    const float* k  = (const float*)d_in[1];
    const float* v  = (const float*)d_in[2];
    const float* Wq = (const float*)d_in[3];
    const float* bq = (const float*)d_in[4];
    const float* Wk = (const float*)d_in[5];
    const float* bk = (const float*)d_in[6];
    const float* Wv = (const float*)d_in[7];
    const float* bv = (const float*)d_in[8];
    const float* Wo = (const float*)d_in[9];
    const float* bo = (const float*)d_in[10];
    float* out = (float*)d_out;

    __half *hQ, *hK, *hV, *hC, *a16, *w16, *woh, *wol;
    cudaGetSymbolAddress((void**)&hQ, g_hQ);
    cudaGetSymbolAddress((void**)&hK, g_hK);
    cudaGetSymbolAddress((void**)&hV, g_hV);
    cudaGetSymbolAddress((void**)&hC, g_hC);
    cudaGetSymbolAddress((void**)&a16, g_a16);
    cudaGetSymbolAddress((void**)&w16, g_w16);
    cudaGetSymbolAddress((void**)&woh, g_woh);
    cudaGetSymbolAddress((void**)&wol, g_wol);

    __half* a0 = a16;
    __half* a1 = a16 + (size_t)GM * GK;
    __half* a2 = a16 + 2 * (size_t)GM * GK;
    __half* w0 = w16;
    __half* w1 = w16 + (size_t)GN * GK;
    __half* w2 = w16 + 2 * (size_t)GN * GK;

    const int n4_act = GM * GK / 4;
    const int n4_w   = GN * GK / 4;

    conv_fp16_x3<<<dim3(n4_act / 256, 3), 256>>>(
        (const float4*)q, (const float4*)k, (const float4*)v,
        (half2*)a0, (half2*)a1, (half2*)a2, n4_act);
    conv_fp16_x3<<<dim3(n4_w / 256, 3), 256>>>(
        (const float4*)Wq, (const float4*)Wk, (const float4*)Wv,
        (half2*)w0, (half2*)w1, (half2*)w2, n4_w);
    split_fp16w<<<n4_w / 256, 256>>>((const float4*)Wo,
        (half2*)woh, (half2*)wol, n4_w);

    cudaFuncSetAttribute(gemm_qkv_fp16, cudaFuncAttributeMaxDynamicSharedMemorySize, GEMM_SMEM);
    cudaFuncSetAttribute(gemm_o_fp16, cudaFuncAttributeMaxDynamicSharedMemorySize, GEMM_SMEM);

    gemm_qkv_fp16<<<dim3(GN / BN, GM / BM, 3), 256, GEMM_SMEM>>>(
        a0, a1, a2, w0, w1, w2, bq, bk, bv, hQ, hK, hV);

    cudaFuncSetAttribute(attn_mma, cudaFuncAttributeMaxDynamicSharedMemorySize, ATTN_SMEM);
    attn_mma<<<dim3(SQ / BQ, NH, NB), 256, ATTN_SMEM>>>(hQ, hK, hV, hC);

    gemm_o_fp16<<<dim3(GN / BN, GM / BM), 256, GEMM_SMEM>>>(hC, wol, woh, bo, out);
}

// round 11
// speedup vs baseline: 1.8115x; 1.0749x over previous
#include <cuda_runtime.h>
#include <cuda_fp16.h>
#include <cstdint>
#include <math.h>

// Problem constants
#define GM 8192      // B*S
#define GN 1024      // D_MODEL
#define GK 1024      // D_MODEL
#define SQ 2048      // S
#define NB 4         // B
#define NH 16        // heads
#define DKH 64       // d_k per head

// Scratch (allocation-free rule: __device__ globals)
__device__ __half g_hQ[(size_t)GM * GN];
__device__ __half g_hK[(size_t)GM * GN];
__device__ __half g_hV[(size_t)GM * GN];
__device__ __half g_hC[(size_t)GM * GN];      // fp16 ctx
__device__ __half g_a16[3][(size_t)GM * GK];  // fp16 activations (q,k,v)
__device__ __half g_w16[3][(size_t)GN * GK];  // fp16 weights (Wq,Wk,Wv)
__device__ __half g_wo16[(size_t)GN * GK];    // fp16 Wo

__device__ __forceinline__ uint32_t smem_u32(const void* p) {
    uint32_t a;
    asm("{ .reg .u64 t; cvta.to.shared.u64 t, %1; cvt.u32.u64 %0, t; }"
        : "=r"(a) : "l"(p));
    return a;
}

__device__ __forceinline__ void cp_async16(uint32_t sm, const void* g) {
    asm volatile("cp.async.cg.shared.global [%0], [%1], 16;\n"
                 :: "r"(sm), "l"(g));
}
#define CP_COMMIT() asm volatile("cp.async.commit_group;\n" ::: "memory")
#define CP_WAIT(N)  asm volatile("cp.async.wait_group %0;\n" :: "n"(N) : "memory")

__device__ __forceinline__ void ldmx4(uint32_t* r, uint32_t addr) {
    asm volatile("ldmatrix.sync.aligned.m8n8.x4.shared.b16 {%0,%1,%2,%3}, [%4];"
                 : "=r"(r[0]), "=r"(r[1]), "=r"(r[2]), "=r"(r[3]) : "r"(addr));
}
__device__ __forceinline__ void ldmx4t(uint32_t* r, uint32_t addr) {
    asm volatile("ldmatrix.sync.aligned.m8n8.x4.trans.shared.b16 {%0,%1,%2,%3}, [%4];"
                 : "=r"(r[0]), "=r"(r[1]), "=r"(r[2]), "=r"(r[3]) : "r"(addr));
}

__device__ __forceinline__ void mma_fp(float* c, const uint32_t* a,
                                       uint32_t b0, uint32_t b1) {
    asm volatile(
        "mma.sync.aligned.m16n8k16.row.col.f32.f16.f16.f32 "
        "{%0,%1,%2,%3}, {%4,%5,%6,%7}, {%8,%9}, {%0,%1,%2,%3};"
        : "+f"(c[0]), "+f"(c[1]), "+f"(c[2]), "+f"(c[3])
        : "r"(a[0]), "r"(a[1]), "r"(a[2]), "r"(a[3]), "r"(b0), "r"(b1));
}

__device__ __forceinline__ uint32_t pack_h2(float x, float y) {
    const half2 h = __floats2half2_rn(x, y);
    return *reinterpret_cast<const uint32_t*>(&h);
}

// ============================================================================
// fp32 -> fp16 converts
// ============================================================================
__global__ __launch_bounds__(256) void conv_fp16_x3(
    const float4* __restrict__ s0, const float4* __restrict__ s1,
    const float4* __restrict__ s2, half2* __restrict__ d0,
    half2* __restrict__ d1, half2* __restrict__ d2, int n4)
{
    const int z = blockIdx.y;
    const float4* src = (z == 0) ? s0 : (z == 1) ? s1 : s2;
    half2* dst = (z == 0) ? d0 : (z == 1) ? d1 : d2;
    const int i = blockIdx.x * 256 + threadIdx.x;
    if (i >= n4) return;
    const float4 v = src[i];
    dst[2 * i]     = __floats2half2_rn(v.x, v.y);
    dst[2 * i + 1] = __floats2half2_rn(v.z, v.w);
}

__global__ __launch_bounds__(256) void conv_fp16_1(
    const float4* __restrict__ src, half2* __restrict__ dst, int n4)
{
    const int i = blockIdx.x * 256 + threadIdx.x;
    if (i >= n4) return;
    const float4 v = src[i];
    dst[2 * i]     = __floats2half2_rn(v.x, v.y);
    dst[2 * i + 1] = __floats2half2_rn(v.z, v.w);
}

// ============================================================================
// GEMM geometry: 128x128 tile, BK=64 per stage, 3 stages, 1 sync/iter.
// ============================================================================
#define BM 128
#define BN 128
#define BKC 64
#define PADK 72
#define GEMM_STAGE_HALVES ((BM + BN) * PADK)          // 18432 halves/stage
#define GEMM_SMEM (3 * GEMM_STAGE_HALVES * 2)         // 110592 B

// ============================================================================
// Single-pass fp16 GEMM for Q/K/V projections, fused via blockIdx.z.
// ============================================================================
__global__ __launch_bounds__(256, 2) void gemm_qkv_fp16(
    const __half* __restrict__ A0, const __half* __restrict__ A1,
    const __half* __restrict__ A2, const __half* __restrict__ W0,
    const __half* __restrict__ W1, const __half* __restrict__ W2,
    const float* __restrict__ b0p, const float* __restrict__ b1p,
    const float* __restrict__ b2p, __half* __restrict__ C0,
    __half* __restrict__ C1, __half* __restrict__ C2)
{
    extern __shared__ __half dynsm[];
    __half* smA = dynsm;                         // [3][BM*PADK]
    __half* smB = dynsm + 3 * BM * PADK;         // [3][BN*PADK]

    const int z = blockIdx.z;
    const __half* A = (z == 0) ? A0 : (z == 1) ? A1 : A2;
    const __half* W = (z == 0) ? W0 : (z == 1) ? W1 : W2;
    const float* bias = (z == 0) ? b0p : (z == 1) ? b1p : b2p;
    __half* C = (z == 0) ? C0 : (z == 1) ? C1 : C2;

    const int tid  = threadIdx.x;
    const int wid  = tid >> 5;
    const int lane = tid & 31;
    const int wm   = wid & 3;
    const int wn   = wid >> 2;
    const int m0   = blockIdx.y * BM;
    const int n0   = blockIdx.x * BN;

    const int crow = tid >> 1;           // 0..127 (2 threads/row)
    const int cs0  = (tid & 1) * 4;      // 4 x 16B segments per thread
    const int lr = lane & 15;
    const int lc = (lane >> 4) * 8;

    float acc[2][8][4];
#pragma unroll
    for (int i = 0; i < 2; i++)
#pragma unroll
        for (int j = 0; j < 8; j++)
#pragma unroll
            for (int k = 0; k < 4; k++) acc[i][j][k] = 0.0f;

    const uint32_t smA0 = smem_u32(smA);
    const uint32_t smB0 = smem_u32(smB);

    auto issue_copy = [&](int it, int st) {
        const int kb = it * BKC;
        const __half* Ab = A + (size_t)(m0 + crow) * GK + kb;
        const __half* Bb = W + (size_t)(n0 + crow) * GK + kb;
        const uint32_t sa = smA0 + (st * BM * PADK + crow * PADK) * 2;
        const uint32_t sb = smB0 + (st * BN * PADK + crow * PADK) * 2;
#pragma unroll
        for (int s = 0; s < 4; s++) {
            cp_async16(sa + (cs0 + s) * 16, Ab + (cs0 + s) * 8);
            cp_async16(sb + (cs0 + s) * 16, Bb + (cs0 + s) * 8);
        }
        CP_COMMIT();
    };

    const int NIT1 = GK / BKC;   // 16
    issue_copy(0, 0);
    issue_copy(1, 1);

    for (int it = 0; it < NIT1; it++) {
        const int st = it % 3;
        if (it + 1 < NIT1) { CP_WAIT(1); } else { CP_WAIT(0); }
        __syncthreads();

        const uint32_t baseA = smA0 + st * BM * PADK * 2;
        const uint32_t baseB = smB0 + st * BN * PADK * 2;
#pragma unroll
        for (int ks = 0; ks < 4; ks++) {
            uint32_t a[2][4], b[4][4];
#pragma unroll
            for (int am = 0; am < 2; am++) {
                const int row = wm * 32 + am * 16 + lr;
                ldmx4(a[am], baseA + (row * PADK + ks * 16 + lc) * 2);
            }
#pragma unroll
            for (int bn = 0; bn < 4; bn++) {
                const int row = wn * 64 + bn * 16 + lr;
                ldmx4(b[bn], baseB + (row * PADK + ks * 16 + lc) * 2);
            }
#pragma unroll
            for (int am = 0; am < 2; am++)
#pragma unroll
                for (int bn = 0; bn < 4; bn++) {
                    mma_fp(acc[am][2 * bn + 0], a[am], b[bn][0], b[bn][2]);
                    mma_fp(acc[am][2 * bn + 1], a[am], b[bn][1], b[bn][3]);
                }
        }
        if (it + 2 < NIT1) issue_copy(it + 2, (it + 2) % 3);
    }

    const int er = lane >> 2;
    const int ec = (lane & 3) * 2;
#pragma unroll
    for (int am = 0; am < 2; am++) {
        const int row = m0 + wm * 32 + am * 16 + er;
#pragma unroll
        for (int bn = 0; bn < 8; bn++) {
            const int col = n0 + wn * 64 + bn * 8 + ec;
            const float bx = bias[col], by = bias[col + 1];
            *(half2*)(C + (size_t)row * GN + col) =
                __floats2half2_rn(acc[am][bn][0] + bx, acc[am][bn][1] + by);
            *(half2*)(C + (size_t)(row + 8) * GN + col) =
                __floats2half2_rn(acc[am][bn][2] + bx, acc[am][bn][3] + by);
        }
    }
}

// ============================================================================
// O projection: single-pass fp16 GEMM, fp32 out.
// ============================================================================
__global__ __launch_bounds__(256, 2) void gemm_o_fp16(
    const __half* __restrict__ A, const __half* __restrict__ W,
    const float* __restrict__ bias, float* __restrict__ C)
{
    extern __shared__ __half dynsm[];
    __half* smA = dynsm;
    __half* smB = dynsm + 3 * BM * PADK;

    const int tid  = threadIdx.x;
    const int wid  = tid >> 5;
    const int lane = tid & 31;
    const int wm   = wid & 3;
    const int wn   = wid >> 2;
    const int m0   = blockIdx.y * BM;
    const int n0   = blockIdx.x * BN;

    const int crow = tid >> 1;
    const int cs0  = (tid & 1) * 4;
    const int lr = lane & 15;
    const int lc = (lane >> 4) * 8;

    float acc[2][8][4];
#pragma unroll
    for (int i = 0; i < 2; i++)
#pragma unroll
        for (int j = 0; j < 8; j++)
#pragma unroll
            for (int k = 0; k < 4; k++) acc[i][j][k] = 0.0f;

    const uint32_t smA0 = smem_u32(smA);
    const uint32_t smB0 = smem_u32(smB);

    auto issue_copy = [&](int it, int st) {
        const int kb = it * BKC;
        const __half* Ab = A + (size_t)(m0 + crow) * GK + kb;
        const __half* Bb = W + (size_t)(n0 + crow) * GK + kb;
        const uint32_t sa = smA0 + (st * BM * PADK + crow * PADK) * 2;
        const uint32_t sb = smB0 + (st * BN * PADK + crow * PADK) * 2;
#pragma unroll
        for (int s = 0; s < 4; s++) {
            cp_async16(sa + (cs0 + s) * 16, Ab + (cs0 + s) * 8);
            cp_async16(sb + (cs0 + s) * 16, Bb + (cs0 + s) * 8);
        }
        CP_COMMIT();
    };

    const int NIT1 = GK / BKC;   // 16
    issue_copy(0, 0);
    issue_copy(1, 1);

    for (int it = 0; it < NIT1; it++) {
        const int st = it % 3;
        if (it + 1 < NIT1) { CP_WAIT(1); } else { CP_WAIT(0); }
        __syncthreads();

        const uint32_t baseA = smA0 + st * BM * PADK * 2;
        const uint32_t baseB = smB0 + st * BN * PADK * 2;
#pragma unroll
        for (int ks = 0; ks < 4; ks++) {
            uint32_t a[2][4], b[4][4];
#pragma unroll
            for (int am = 0; am < 2; am++) {
                const int row = wm * 32 + am * 16 + lr;
                ldmx4(a[am], baseA + (row * PADK + ks * 16 + lc) * 2);
            }
#pragma unroll
            for (int bn = 0; bn < 4; bn++) {
                const int row = wn * 64 + bn * 16 + lr;
                ldmx4(b[bn], baseB + (row * PADK + ks * 16 + lc) * 2);
            }
#pragma unroll
            for (int am = 0; am < 2; am++)
#pragma unroll
                for (int bn = 0; bn < 4; bn++) {
                    mma_fp(acc[am][2 * bn + 0], a[am], b[bn][0], b[bn][2]);
                    mma_fp(acc[am][2 * bn + 1], a[am], b[bn][1], b[bn][3]);
                }
        }
        if (it + 2 < NIT1) issue_copy(it + 2, (it + 2) % 3);
    }

    const int er = lane >> 2;
    const int ec = (lane & 3) * 2;
#pragma unroll
    for (int am = 0; am < 2; am++) {
        const int row = m0 + wm * 32 + am * 16 + er;
#pragma unroll
        for (int bn = 0; bn < 8; bn++) {
            const int col = n0 + wn * 64 + bn * 8 + ec;
            const float bx = bias[col], by = bias[col + 1];
            *(float2*)(C + (size_t)row * GN + col) =
                make_float2(acc[am][bn][0] + bx, acc[am][bn][1] + by);
            *(float2*)(C + (size_t)(row + 8) * GN + col) =
                make_float2(acc[am][bn][2] + bx, acc[am][bn][3] + by);
        }
    }
}

// ============================================================================
// Fused flash attention, fp16 mma.sync, BKV=128, register-resident P.
//   Unchanged from R8/R9 (passing, 1 CTA/SM).
// ============================================================================
#define BQ 128
#define BKV 128
#define QS 72
#define NTKV (SQ / BKV)   // 16
#define ATTN_SMEM ((BQ * QS + 4 * BKV * QS) * 2)   // 92160 B

__global__ __launch_bounds__(256, 1) void attn_mma(
    const __half* __restrict__ Qh, const __half* __restrict__ Kh,
    const __half* __restrict__ Vh, __half* __restrict__ Ctx)
{
    extern __shared__ __half sm[];
    __half* sQ = sm;                   // [128][QS]
    __half* sK = sQ + BQ * QS;         // [2][128][QS]
    __half* sV = sK + 2 * BKV * QS;    // [2][128][QS]

    const int tid  = threadIdx.x;
    const int wid  = tid >> 5;
    const int lane = tid & 31;
    const int lr   = lane & 15;
    const int lc   = (lane >> 4) * 8;
    const int er   = lane >> 2;
    const int ec   = (lane & 3) * 2;
    const int wrow = wid * 16;

    const int q0 = blockIdx.x * BQ;
    const size_t hb = ((size_t)blockIdx.z * SQ) * (size_t)GN + (size_t)blockIdx.y * DKH;

    const uint32_t sQb = smem_u32(sQ);
    const uint32_t sKb = smem_u32(sK);
    const uint32_t sVb = smem_u32(sV);

    const int crow = tid >> 1;
    const int cs0  = (tid & 1) * 4;

    auto loadKV = [&](int kt, int st) {
        const __half* kp = Kh + hb + (size_t)(kt * BKV + crow) * GN;
        const __half* vp = Vh + hb + (size_t)(kt * BKV + crow) * GN;
        const uint32_t dk = sKb + (st * BKV * QS + crow * QS) * 2;
        const uint32_t dv = sVb + (st * BKV * QS + crow * QS) * 2;
#pragma unroll
        for (int s = 0; s < 4; s++) {
            cp_async16(dk + (cs0 + s) * 16, kp + (cs0 + s) * 8);
            cp_async16(dv + (cs0 + s) * 16, vp + (cs0 + s) * 8);
        }
    };

    {
        const __half* qp = Qh + hb + (size_t)(q0 + crow) * GN;
        const uint32_t dq = sQb + (crow * QS) * 2;
#pragma unroll
        for (int s = 0; s < 4; s++)
            cp_async16(dq + (cs0 + s) * 16, qp + (cs0 + s) * 8);
    }
    loadKV(0, 0);
    CP_COMMIT();
    loadKV(1, 1);
    CP_COMMIT();

    float m0r = -1.0e30f, m1r = -1.0e30f, l0 = 0.0f, l1 = 0.0f;
    float o[8][4];
#pragma unroll
    for (int j = 0; j < 8; j++)
#pragma unroll
        for (int k = 0; k < 4; k++) o[j][k] = 0.0f;

    uint32_t aq[4][4];   // Q fragments, loaded once

    for (int kt = 0; kt < NTKV; kt++) {
        if (kt < NTKV - 1) { CP_WAIT(1); } else { CP_WAIT(0); }
        __syncthreads();
        if (kt == 0) {
#pragma unroll
            for (int ks = 0; ks < 4; ks++)
                ldmx4(aq[ks], sQb + ((wrow + lr) * QS + ks * 16 + lc) * 2);
        }
        const int st = kt & 1;
        const uint32_t kbase = sKb + st * BKV * QS * 2;
        const uint32_t vbase = sVb + st * BKV * QS * 2;

        // ---- S = Q K^T (16 x 128 per warp) ----
        float s[16][4];
#pragma unroll
        for (int t = 0; t < 16; t++)
#pragma unroll
            for (int k = 0; k < 4; k++) s[t][k] = 0.0f;

#pragma unroll
        for (int ks = 0; ks < 4; ks++) {
#pragma unroll
            for (int nt = 0; nt < 8; nt++) {
                uint32_t b[4];
                ldmx4(b, kbase + ((nt * 16 + lr) * QS + ks * 16 + lc) * 2);
                mma_fp(s[2 * nt + 0], aq[ks], b[0], b[2]);
                mma_fp(s[2 * nt + 1], aq[ks], b[1], b[3]);
            }
        }

        // ---- online softmax; P packed into A-frag registers ----
        float mx0 = -1.0e30f, mx1 = -1.0e30f;
#pragma unroll
        for (int t = 0; t < 16; t++) {
            mx0 = fmaxf(mx0, fmaxf(s[t][0], s[t][1]));
            mx1 = fmaxf(mx1, fmaxf(s[t][2], s[t][3]));
        }
        mx0 = fmaxf(mx0, __shfl_xor_sync(0xffffffffu, mx0, 1));
        mx0 = fmaxf(mx0, __shfl_xor_sync(0xffffffffu, mx0, 2));
        mx1 = fmaxf(mx1, __shfl_xor_sync(0xffffffffu, mx1, 1));
        mx1 = fmaxf(mx1, __shfl_xor_sync(0xffffffffu, mx1, 2));
        mx0 *= 0.125f;
        mx1 *= 0.125f;
        const float mn0 = fmaxf(m0r, mx0);
        const float mn1 = fmaxf(m1r, mx1);
        const float c0 = __expf(m0r - mn0);
        const float c1 = __expf(m1r - mn1);

        float rs0 = 0.0f, rs1 = 0.0f;
        uint32_t pw[16][2];
#pragma unroll
        for (int t = 0; t < 16; t++) {
            const float p00 = __expf(fmaf(s[t][0], 0.125f, -mn0));
            const float p01 = __expf(fmaf(s[t][1], 0.125f, -mn0));
            const float p10 = __expf(fmaf(s[t][2], 0.125f, -mn1));
            const float p11 = __expf(fmaf(s[t][3], 0.125f, -mn1));
            rs0 += p00 + p01;
            rs1 += p10 + p11;
            pw[t][0] = pack_h2(p00, p01);
            pw[t][1] = pack_h2(p10, p11);
        }
        rs0 += __shfl_xor_sync(0xffffffffu, rs0, 1);
        rs0 += __shfl_xor_sync(0xffffffffu, rs0, 2);
        rs1 += __shfl_xor_sync(0xffffffffu, rs1, 1);
        rs1 += __shfl_xor_sync(0xffffffffu, rs1, 2);
        l0 = l0 * c0 + rs0;
        l1 = l1 * c1 + rs1;
        m0r = mn0;
        m1r = mn1;
#pragma unroll
        for (int j = 0; j < 8; j++) {
            o[j][0] *= c0; o[j][1] *= c0;
            o[j][2] *= c1; o[j][3] *= c1;
        }

        // ---- O += P V (P from registers, V via ldmatrix.trans) ----
#pragma unroll
        for (int j = 0; j < 8; j++) {      // 16-key chunks
            const uint32_t pa[4] = {pw[2 * j][0], pw[2 * j][1],
                                    pw[2 * j + 1][0], pw[2 * j + 1][1]};
#pragma unroll
            for (int dt = 0; dt < 4; dt++) {
                uint32_t vb[4];
                ldmx4t(vb, vbase + ((j * 16 + lr) * QS + dt * 16 + lc) * 2);
                mma_fp(o[2 * dt + 0], pa, vb[0], vb[1]);
                mma_fp(o[2 * dt + 1], pa, vb[2], vb[3]);
            }
        }
        __syncthreads();
        if (kt + 2 < NTKV) {
            loadKV(kt + 2, st);
            CP_COMMIT();
        }
    }

    const float inv0 = 1.0f / l0;
    const float inv1 = 1.0f / l1;
    const int row0 = q0 + wrow + er;
#pragma unroll
    for (int j = 0; j < 8; j++) {
        const int col = j * 8 + ec;
        __half* p0 = Ctx + hb + (size_t)row0 * GN + col;
        __half* p1 = Ctx + hb + (size_t)(row0 + 8) * GN + col;
        *(half2*)p0 = __floats2half2_rn(o[j][0] * inv0, o[j][1] * inv0);
        *(half2*)p1 = __floats2half2_rn(o[j][2] * inv1, o[j][3] * inv1);
    }
}

// ============================================================================
// Launch
// ============================================================================
extern "C" void kernel_launch(void* const* d_in, const int* in_sizes, int n_in,
                              void* d_out, int out_size)
{
    const float* q  = (const float*)d_in[0];
    const float* k  = (const float*)d_in[1];
    const float* v  = (const float*)d_in[2];
    const float* Wq = (const float*)d_in[3];
    const float* bq = (const float*)d_in[4];
    const float* Wk = (const float*)d_in[5];
    const float* bk = (const float*)d_in[6];
    const float* Wv = (const float*)d_in[7];
    const float* bv = (const float*)d_in[8];
    const float* Wo = (const float*)d_in[9];
    const float* bo = (const float*)d_in[10];
    float* out = (float*)d_out;

    __half *hQ, *hK, *hV, *hC, *a16, *w16, *wo16;
    cudaGetSymbolAddress((void**)&hQ, g_hQ);
    cudaGetSymbolAddress((void**)&hK, g_hK);
    cudaGetSymbolAddress((void**)&hV, g_hV);
    cudaGetSymbolAddress((void**)&hC, g_hC);
    cudaGetSymbolAddress((void**)&a16, g_a16);
    cudaGetSymbolAddress((void**)&w16, g_w16);
    cudaGetSymbolAddress((void**)&wo16, g_wo16);

    __half* a0 = a16;
    __half* a1 = a16 + (size_t)GM * GK;
    __half* a2 = a16 + 2 * (size_t)GM * GK;
    __half* w0 = w16;
    __half* w1 = w16 + (size_t)GN * GK;
    __half* w2 = w16 + 2 * (size_t)GN * GK;

    const int n4_act = GM * GK / 4;
    const int n4_w   = GN * GK / 4;

    conv_fp16_x3<<<dim3(n4_act / 256, 3), 256>>>(
        (const float4*)q, (const float4*)k, (const float4*)v,
        (half2*)a0, (half2*)a1, (half2*)a2, n4_act);
    conv_fp16_x3<<<dim3(n4_w / 256, 3), 256>>>(
        (const float4*)Wq, (const float4*)Wk, (const float4*)Wv,
        (half2*)w0, (half2*)w1, (half2*)w2, n4_w);
    conv_fp16_1<<<n4_w / 256, 256>>>((const float4*)Wo, (half2*)wo16, n4_w);

    cudaFuncSetAttribute(gemm_qkv_fp16, cudaFuncAttributeMaxDynamicSharedMemorySize, GEMM_SMEM);
    cudaFuncSetAttribute(gemm_o_fp16, cudaFuncAttributeMaxDynamicSharedMemorySize, GEMM_SMEM);

    gemm_qkv_fp16<<<dim3(GN / BN, GM / BM, 3), 256, GEMM_SMEM>>>(
        a0, a1, a2, w0, w1, w2, bq, bk, bv, hQ, hK, hV);

    cudaFuncSetAttribute(attn_mma, cudaFuncAttributeMaxDynamicSharedMemorySize, ATTN_SMEM);
    attn_mma<<<dim3(SQ / BQ, NH, NB), 256, ATTN_SMEM>>>(hQ, hK, hV, hC);

    gemm_o_fp16<<<dim3(GN / BN, GM / BM), 256, GEMM_SMEM>>>(hC, wo16, bo, out);
}